// round 14
// baseline (speedup 1.0000x reference)
#include <cuda_runtime.h>
#include <cuda_bf16.h>
#include <math.h>
#include <stdint.h>

#define Bq 16
#define Nq 128
#define Hq 64
#define Mq 64
#define INq 32
#define Tq 32
#define NE (Bq*Nq*Nq)        /* 262144 edges */
#define NNODE (Bq*Nq)        /* 2048 nodes  */
#define KO 8192              /* 128*64      */
#define KBIG (Nq*128)        /* 16384       */
#define SPLITS 32
#define KS (KBIG/SPLITS)     /* 512         */

typedef unsigned long long ull;
typedef unsigned int uint32;

// ---- packed f32x2 helpers (sm_103a) ---------------------------------------
#define PACK_DUP(d, s) asm("mov.b64 %0, {%1, %1};" : "=l"(d) : "r"(__float_as_uint(s)))
#define FMA_X2(d, a, b) asm("fma.rn.f32x2 %0, %1, %2, %0;" : "+l"(d) : "l"(a), "l"(b))
#define UNPACK2(lo, hi, s) asm("mov.b64 {%0, %1}, %2;" : "=r"(lo), "=r"(hi) : "l"(s))

// ---- mma.sync / ldmatrix helpers ------------------------------------------
__device__ __forceinline__ uint32 smem_u32(const void* p) {
    uint32 a;
    asm("{ .reg .u64 t; cvta.to.shared.u64 t, %1; cvt.u32.u64 %0, t; }" : "=r"(a) : "l"(p));
    return a;
}

#define LDSM4(r0,r1,r2,r3,addr) \
    asm volatile("ldmatrix.sync.aligned.m8n8.x4.shared.b16 {%0,%1,%2,%3}, [%4];" \
        : "=r"(r0),"=r"(r1),"=r"(r2),"=r"(r3) : "r"(addr))

__device__ __forceinline__ void mma_bf16(float* c, const uint32* a, uint32 b0, uint32 b1){
    asm volatile("mma.sync.aligned.m16n8k16.row.col.f32.bf16.bf16.f32 "
        "{%0,%1,%2,%3},{%4,%5,%6,%7},{%8,%9},{%0,%1,%2,%3};"
        : "+f"(c[0]),"+f"(c[1]),"+f"(c[2]),"+f"(c[3])
        : "r"(a[0]),"r"(a[1]),"r"(a[2]),"r"(a[3]),"r"(b0),"r"(b1));
}

__device__ __forceinline__ uint32 packsplit(float v){
    __nv_bfloat16 h = __float2bfloat16(v);
    float r = v - __bfloat162float(h);
    __nv_bfloat16 l = __float2bfloat16(r);
    return (uint32)__bfloat16_as_ushort(h) | ((uint32)__bfloat16_as_ushort(l) << 16);
}

#define SPLIT8(e0,e1,e2,e3,e4,e5,e6,e7,H,L) do { \
    H.x=(e0&0xffffu)|(e1<<16); H.y=(e2&0xffffu)|(e3<<16); \
    H.z=(e4&0xffffu)|(e5<<16); H.w=(e6&0xffffu)|(e7<<16); \
    L.x=(e0>>16)|(e1&0xffff0000u); L.y=(e2>>16)|(e3&0xffff0000u); \
    L.z=(e4>>16)|(e5&0xffff0000u); L.w=(e6>>16)|(e7&0xffff0000u); \
} while(0)

#define MMA_TERMS(c0, c1, ah, al, bh, bl) do { \
    mma_bf16(c0, ah, bh[0], bh[1]); \
    mma_bf16(c0, ah, bl[0], bl[1]); \
    mma_bf16(c0, al, bh[0], bh[1]); \
    mma_bf16(c1, ah, bh[2], bh[3]); \
    mma_bf16(c1, ah, bl[2], bl[3]); \
    mma_bf16(c1, al, bh[2], bh[3]); \
} while(0)

// ---------------- scratch (static device globals; no allocation) ----------
__device__ uint32 d_e256p[(long)NE*256]; // mlp1 out, packed bf16 hi/lo
__device__ uint32 d_fp[(long)NE*128];    // edge features, packed bf16 hi/lo
__device__ uint32 d_w1p[256*128];        // W1^T packed [NOUT=256][K=128]
__device__ uint32 d_w2p[128*256];        // W2^T packed [NOUT=128][K=256]
__device__ uint32 d_w3p[KO*64];          // W3t packed [n=8192][k=64]
__device__ float d_h[NNODE*Hq];
__device__ uint32 d_hp[NNODE*Hq];        // h packed bf16 hi/lo
__device__ uint32 d_g[(long)NNODE*KO];   // g packed bf16 hi/lo
__device__ float d_part[(long)SPLITS*Bq*Nq*Mq];
__device__ float d_WihT[Hq*192];
__device__ float d_WhhT[Hq*192];
__device__ float d_cat[NNODE*96];
__device__ float d_t1[NNODE*256];
__device__ float d_t2[NNODE*256];
__device__ float d_v1[NNODE*256];
__device__ float d_v2[NNODE*256];
__device__ float d_gatel[NNODE*Tq];
__device__ float d_val[NNODE*Tq];
__device__ float d_res[Bq*Tq];

// ==== 64-row MLP layer kernels (R8 config: 256 thr, 8 warps, 32x32 tiles) ==
#define KP64 136
#define M64_SMEM ((2*64*KP64 + 2*128*KP64)*2)   /* 104448 */

__global__ __launch_bounds__(256)
void mlp1_mma64(const float* __restrict__ am,
                const float* __restrict__ We0, const float* __restrict__ be0,
                const uint32* __restrict__ Wp, const float* __restrict__ bias,
                uint32* __restrict__ Cout)
{
    extern __shared__ __align__(16) char smem[];
    __nv_bfloat16* Ah = (__nv_bfloat16*)smem;          // [64][KP64]
    __nv_bfloat16* Al = Ah + 64*KP64;
    __nv_bfloat16* Wh = Al + 64*KP64;                  // [128][KP64]
    __nv_bfloat16* Wl = Wh + 128*KP64;

    const int tid = threadIdx.x;
    const int wid = tid >> 5, lane = tid & 31;
    const long bm = (long)blockIdx.x * 64;
    const int m0 = (wid & 1) * 32;
    const int cg = wid >> 1;                           // 4 col groups of 32

    const uint32 sAh = smem_u32(Ah), sAl = smem_u32(Al);
    const uint32 sWh = smem_u32(Wh), sWl = smem_u32(Wl);

    {
        int r = tid >> 2, seg = tid & 3;
        float4 a = *(const float4*)&am[(bm + r) * 4];
        #pragma unroll
        for (int c4 = 0; c4 < 8; c4++) {
            int c = seg*32 + c4*4;
            ull hv = 0, lv = 0;
            #pragma unroll
            for (int j = 0; j < 4; j++) {
                int n = c + j;
                float v = be0[n];
                v = fmaf(a.x, We0[n], v);
                v = fmaf(a.y, We0[128+n], v);
                v = fmaf(a.z, We0[256+n], v);
                v = fmaf(a.w, We0[384+n], v);
                v = fmaxf(v, 0.f);
                uint32 p = packsplit(v);
                hv |= ((ull)(p & 0xffffu)) << (16*j);
                lv |= ((ull)(p >> 16)) << (16*j);
            }
            *(ull*)&Ah[r*KP64 + c] = hv;
            *(ull*)&Al[r*KP64 + c] = lv;
        }
    }

    const int alrow = lane & 15;
    const uint32 a_koff = ((lane >> 4) << 3);
    const int brow = ((lane >> 4) & 1) * 8 + (lane & 7);
    const uint32 b_koff = ((lane >> 3) & 1) * 8;
    const int erow = (lane >> 2);
    const int ecol = (lane & 3) << 1;

    #pragma unroll 1
    for (int nh = 0; nh < 2; nh++) {
        __syncthreads();
        for (int gi = tid; gi < 128*16; gi += 256) {
            int n = gi >> 4, k = (gi & 15) * 8;
            const uint32* src = &Wp[(long)(nh*128 + n)*128 + k];
            uint4 v0 = *(const uint4*)src, v1 = *(const uint4*)(src+4);
            uint4 H, L;
            SPLIT8(v0.x,v0.y,v0.z,v0.w,v1.x,v1.y,v1.z,v1.w,H,L);
            *(uint4*)&Wh[n*KP64 + k] = H;
            *(uint4*)&Wl[n*KP64 + k] = L;
        }
        __syncthreads();

        float acc[8][4] = {};
        #pragma unroll
        for (int ks = 0; ks < 8; ks++) {
            const uint32 kk = ks * 16;
            uint32 ah[2][4], al[2][4];
            #pragma unroll
            for (int mt = 0; mt < 2; mt++) {
                uint32 ab = (uint32)(((m0 + mt*16 + alrow)*KP64 + kk + a_koff) << 1);
                LDSM4(ah[mt][0],ah[mt][1],ah[mt][2],ah[mt][3], sAh + ab);
                LDSM4(al[mt][0],al[mt][1],al[mt][2],al[mt][3], sAl + ab);
            }
            #pragma unroll
            for (int g = 0; g < 2; g++) {
                int n0 = cg*32 + g*16;
                uint32 bh[4], bl[4];
                uint32 bb = (uint32)(((n0 + brow)*KP64 + kk + b_koff) << 1);
                LDSM4(bh[0],bh[1],bh[2],bh[3], sWh + bb);
                LDSM4(bl[0],bl[1],bl[2],bl[3], sWl + bb);
                #pragma unroll
                for (int mt = 0; mt < 2; mt++)
                    MMA_TERMS(acc[mt*4+g*2], acc[mt*4+g*2+1], ah[mt], al[mt], bh, bl);
            }
        }
        #pragma unroll
        for (int mt = 0; mt < 2; mt++) {
            long r0 = bm + m0 + mt*16 + erow;
            #pragma unroll
            for (int g = 0; g < 2; g++)
                #pragma unroll
                for (int hcol = 0; hcol < 2; hcol++) {
                    int t = mt*4 + g*2 + hcol;
                    int col = nh*128 + cg*32 + g*16 + hcol*8 + ecol;
                    float b0 = bias[col], b1 = bias[col+1];
                    float v0 = fmaxf(acc[t][0]+b0, 0.f), v1 = fmaxf(acc[t][1]+b1, 0.f);
                    float v2 = fmaxf(acc[t][2]+b0, 0.f), v3 = fmaxf(acc[t][3]+b1, 0.f);
                    *(uint2*)&Cout[r0*256 + col]     = make_uint2(packsplit(v0), packsplit(v1));
                    *(uint2*)&Cout[(r0+8)*256 + col] = make_uint2(packsplit(v2), packsplit(v3));
                }
        }
    }
}

__global__ __launch_bounds__(256)
void mlp2_mma64(const uint32* __restrict__ Ap, const uint32* __restrict__ Wp,
                const float* __restrict__ bias, uint32* __restrict__ Cout)
{
    extern __shared__ __align__(16) char smem[];
    __nv_bfloat16* Ah = (__nv_bfloat16*)smem;          // [64][KP64]
    __nv_bfloat16* Al = Ah + 64*KP64;
    __nv_bfloat16* Wh = Al + 64*KP64;                  // [128][KP64]
    __nv_bfloat16* Wl = Wh + 128*KP64;

    const int tid = threadIdx.x;
    const int wid = tid >> 5, lane = tid & 31;
    const long bm = (long)blockIdx.x * 64;
    const int m0 = (wid & 1) * 32;
    const int cg = wid >> 1;

    const uint32 sAh = smem_u32(Ah), sAl = smem_u32(Al);
    const uint32 sWh = smem_u32(Wh), sWl = smem_u32(Wl);

    const int alrow = lane & 15;
    const uint32 a_koff = ((lane >> 4) << 3);
    const int brow = ((lane >> 4) & 1) * 8 + (lane & 7);
    const uint32 b_koff = ((lane >> 3) & 1) * 8;

    float acc[8][4] = {};

    #pragma unroll 1
    for (int ck = 0; ck < 2; ck++) {
        __syncthreads();
        for (int gi = tid; gi < 64*16; gi += 256) {
            int r = gi >> 4, k = (gi & 15) * 8;
            const uint32* src = &Ap[(bm + r)*256 + ck*128 + k];
            uint4 v0 = *(const uint4*)src, v1 = *(const uint4*)(src+4);
            uint4 H, L;
            SPLIT8(v0.x,v0.y,v0.z,v0.w,v1.x,v1.y,v1.z,v1.w,H,L);
            *(uint4*)&Ah[r*KP64 + k] = H;
            *(uint4*)&Al[r*KP64 + k] = L;
        }
        for (int gi = tid; gi < 128*16; gi += 256) {
            int n = gi >> 4, k = (gi & 15) * 8;
            const uint32* src = &Wp[(long)n*256 + ck*128 + k];
            uint4 v0 = *(const uint4*)src, v1 = *(const uint4*)(src+4);
            uint4 H, L;
            SPLIT8(v0.x,v0.y,v0.z,v0.w,v1.x,v1.y,v1.z,v1.w,H,L);
            *(uint4*)&Wh[n*KP64 + k] = H;
            *(uint4*)&Wl[n*KP64 + k] = L;
        }
        __syncthreads();

        #pragma unroll
        for (int ks = 0; ks < 8; ks++) {
            const uint32 kk = ks * 16;
            uint32 ah[2][4], al[2][4];
            #pragma unroll
            for (int mt = 0; mt < 2; mt++) {
                uint32 ab = (uint32)(((m0 + mt*16 + alrow)*KP64 + kk + a_koff) << 1);
                LDSM4(ah[mt][0],ah[mt][1],ah[mt][2],ah[mt][3], sAh + ab);
                LDSM4(al[mt][0],al[mt][1],al[mt][2],al[mt][3], sAl + ab);
            }
            #pragma unroll
            for (int g = 0; g < 2; g++) {
                int n0 = cg*32 + g*16;
                uint32 bh[4], bl[4];
                uint32 bb = (uint32)(((n0 + brow)*KP64 + kk + b_koff) << 1);
                LDSM4(bh[0],bh[1],bh[2],bh[3], sWh + bb);
                LDSM4(bl[0],bl[1],bl[2],bl[3], sWl + bb);
                #pragma unroll
                for (int mt = 0; mt < 2; mt++)
                    MMA_TERMS(acc[mt*4+g*2], acc[mt*4+g*2+1], ah[mt], al[mt], bh, bl);
            }
        }
    }

    const int erow = (lane >> 2), ecol = (lane & 3) << 1;
    #pragma unroll
    for (int mt = 0; mt < 2; mt++) {
        long r0 = bm + m0 + mt*16 + erow;
        #pragma unroll
        for (int g = 0; g < 2; g++)
            #pragma unroll
            for (int hcol = 0; hcol < 2; hcol++) {
                int t = mt*4 + g*2 + hcol;
                int col = cg*32 + g*16 + hcol*8 + ecol;
                float b0 = bias[col], b1 = bias[col+1];
                float v0 = fmaxf(acc[t][0]+b0, 0.f), v1 = fmaxf(acc[t][1]+b1, 0.f);
                float v2 = fmaxf(acc[t][2]+b0, 0.f), v3 = fmaxf(acc[t][3]+b1, 0.f);
                *(uint2*)&Cout[r0*128 + col]     = make_uint2(packsplit(v0), packsplit(v1));
                *(uint2*)&Cout[(r0+8)*128 + col] = make_uint2(packsplit(v2), packsplit(v3));
            }
    }
}

// ====== g-GEMM on tensor path: g[2048,8192] = hp[2048,64] @ w3p^T ==========
#define KPG 72
#define GMMA_SMEM ((2*64*KPG + 2*128*KPG)*2)   /* 55296 */

__global__ __launch_bounds__(256)
void gmma(const uint32* __restrict__ hp, const uint32* __restrict__ w3p,
          uint32* __restrict__ g)
{
    extern __shared__ __align__(16) char smem[];
    __nv_bfloat16* Ah = (__nv_bfloat16*)smem;          // [64][KPG]
    __nv_bfloat16* Al = Ah + 64*KPG;
    __nv_bfloat16* Wh = Al + 64*KPG;                   // [128][KPG]
    __nv_bfloat16* Wl = Wh + 128*KPG;

    const int tid = threadIdx.x;
    const int wid = tid >> 5, lane = tid & 31;
    const long bm = (long)blockIdx.y * 64;
    const int bn = blockIdx.x * 128;
    const int m0 = (wid & 1) * 32;
    const int cg = wid >> 1;

    const uint32 sAh = smem_u32(Ah), sAl = smem_u32(Al);
    const uint32 sWh = smem_u32(Wh), sWl = smem_u32(Wl);

    for (int gi = tid; gi < 64*8; gi += 256) {
        int r = gi >> 3, k = (gi & 7) * 8;
        const uint32* src = &hp[(bm + r)*64 + k];
        uint4 v0 = *(const uint4*)src, v1 = *(const uint4*)(src+4);
        uint4 H, L;
        SPLIT8(v0.x,v0.y,v0.z,v0.w,v1.x,v1.y,v1.z,v1.w,H,L);
        *(uint4*)&Ah[r*KPG + k] = H;
        *(uint4*)&Al[r*KPG + k] = L;
    }
    for (int gi = tid; gi < 128*8; gi += 256) {
        int n = gi >> 3, k = (gi & 7) * 8;
        const uint32* src = &w3p[(long)(bn + n)*64 + k];
        uint4 v0 = *(const uint4*)src, v1 = *(const uint4*)(src+4);
        uint4 H, L;
        SPLIT8(v0.x,v0.y,v0.z,v0.w,v1.x,v1.y,v1.z,v1.w,H,L);
        *(uint4*)&Wh[n*KPG + k] = H;
        *(uint4*)&Wl[n*KPG + k] = L;
    }
    __syncthreads();

    const int alrow = lane & 15;
    const uint32 a_koff = ((lane >> 4) << 3);
    const int brow = ((lane >> 4) & 1) * 8 + (lane & 7);
    const uint32 b_koff = ((lane >> 3) & 1) * 8;

    float acc[8][4] = {};
    #pragma unroll
    for (int ks = 0; ks < 4; ks++) {
        const uint32 kk = ks * 16;
        uint32 ah[2][4], al[2][4];
        #pragma unroll
        for (int mt = 0; mt < 2; mt++) {
            uint32 ab = (uint32)(((m0 + mt*16 + alrow)*KPG + kk + a_koff) << 1);
            LDSM4(ah[mt][0],ah[mt][1],ah[mt][2],ah[mt][3], sAh + ab);
            LDSM4(al[mt][0],al[mt][1],al[mt][2],al[mt][3], sAl + ab);
        }
        #pragma unroll
        for (int gg = 0; gg < 2; gg++) {
            int n0 = cg*32 + gg*16;
            uint32 bh[4], bl[4];
            uint32 bb = (uint32)(((n0 + brow)*KPG + kk + b_koff) << 1);
            LDSM4(bh[0],bh[1],bh[2],bh[3], sWh + bb);
            LDSM4(bl[0],bl[1],bl[2],bl[3], sWl + bb);
            #pragma unroll
            for (int mt = 0; mt < 2; mt++)
                MMA_TERMS(acc[mt*4+gg*2], acc[mt*4+gg*2+1], ah[mt], al[mt], bh, bl);
        }
    }

    const int erow = (lane >> 2), ecol = (lane & 3) << 1;
    #pragma unroll
    for (int mt = 0; mt < 2; mt++) {
        long r0 = bm + m0 + mt*16 + erow;
        #pragma unroll
        for (int gg = 0; gg < 2; gg++)
            #pragma unroll
            for (int hcol = 0; hcol < 2; hcol++) {
                int t = mt*4 + gg*2 + hcol;
                int col = bn + cg*32 + gg*16 + hcol*8 + ecol;
                *(uint2*)&g[r0*KO + col]      = make_uint2(packsplit(acc[t][0]), packsplit(acc[t][1]));
                *(uint2*)&g[(r0+8)*KO + col]  = make_uint2(packsplit(acc[t][2]), packsplit(acc[t][3]));
            }
    }
}

// ============== split-K msg contraction via mma (bf16 3-term) ==============
#define SKP 136
#define SPLITK_SMEM ((2*128*SKP + 2*64*SKP)*2)  /* 104448 */

__global__ __launch_bounds__(256)
void splitk_mma(const uint32* __restrict__ fp, const uint32* __restrict__ gp,
                float* __restrict__ part)
{
    extern __shared__ __align__(16) char smem[];
    __nv_bfloat16* Ah  = (__nv_bfloat16*)smem;          // [128][SKP]
    __nv_bfloat16* Al  = Ah + 128*SKP;
    __nv_bfloat16* Bth = Al + 128*SKP;                  // [64][SKP]
    __nv_bfloat16* Btl = Bth + 64*SKP;

    const int s = blockIdx.x, b = blockIdx.y;
    const int tid = threadIdx.x;
    const int wid = tid >> 5, lane = tid & 31;
    const int m0 = (wid & 3) * 32;
    const int cg = wid >> 2;

    const uint32 sAh = smem_u32(Ah),  sAl = smem_u32(Al);
    const uint32 sBh = smem_u32(Bth), sBl = smem_u32(Btl);

    const int alrow = lane & 15;
    const uint32 a_koff = ((lane >> 4) << 3);
    const int brow = ((lane >> 4) & 1) * 8 + (lane & 7);
    const uint32 b_koff = ((lane >> 3) & 1) * 8;

    float acc[8][4] = {};

    #pragma unroll 1
    for (int ck = 0; ck < KS/128; ck++) {
        const int k0 = s*KS + ck*128;
        if (ck > 0) __syncthreads();

        const uint32* Abase = fp + (long)b*Nq*KBIG + k0;
        for (int gi = tid; gi < 128*16; gi += 256) {
            int r = gi >> 4, k = (gi & 15) * 8;
            const uint32* src = Abase + (long)r*KBIG + k;
            uint4 v0 = *(const uint4*)src, v1 = *(const uint4*)(src+4);
            uint4 H, L;
            SPLIT8(v0.x,v0.y,v0.z,v0.w,v1.x,v1.y,v1.z,v1.w,H,L);
            *(uint4*)&Ah[r*SKP + k] = H;
            *(uint4*)&Al[r*SKP + k] = L;
        }
        const uint32* Bbase = gp + ((long)b*KBIG + k0) * 64;
        {
            int o = tid & 63, kq = (tid >> 6) * 4;
            #pragma unroll
            for (int it = 0; it < 8; it++) {
                int kk = it*16 + kq;
                uint32 p0 = Bbase[(kk+0)*64 + o];
                uint32 p1 = Bbase[(kk+1)*64 + o];
                uint32 p2 = Bbase[(kk+2)*64 + o];
                uint32 p3 = Bbase[(kk+3)*64 + o];
                ull hv = (ull)(p0&0xffffu) | ((ull)(p1&0xffffu)<<16)
                       | ((ull)(p2&0xffffu)<<32) | ((ull)(p3&0xffffu)<<48);
                ull lv = (ull)(p0>>16) | ((ull)(p1>>16)<<16)
                       | ((ull)(p2>>16)<<32) | ((ull)(p3>>16)<<48);
                *(ull*)&Bth[o*SKP + kk] = hv;
                *(ull*)&Btl[o*SKP + kk] = lv;
            }
        }
        __syncthreads();

        #pragma unroll
        for (int ks = 0; ks < 8; ks++) {
            const uint32 kk = ks * 16;
            uint32 ah[2][4], al[2][4];
            #pragma unroll
            for (int mt = 0; mt < 2; mt++) {
                uint32 ab = (uint32)(((m0 + mt*16 + alrow)*SKP + kk + a_koff) << 1);
                LDSM4(ah[mt][0],ah[mt][1],ah[mt][2],ah[mt][3], sAh + ab);
                LDSM4(al[mt][0],al[mt][1],al[mt][2],al[mt][3], sAl + ab);
            }
            #pragma unroll
            for (int g = 0; g < 2; g++) {
                int n0 = cg*32 + g*16;
                uint32 bh[4], bl[4];
                uint32 bb = (uint32)(((n0 + brow)*SKP + kk + b_koff) << 1);
                LDSM4(bh[0],bh[1],bh[2],bh[3], sBh + bb);
                LDSM4(bl[0],bl[1],bl[2],bl[3], sBl + bb);
                #pragma unroll
                for (int mt = 0; mt < 2; mt++)
                    MMA_TERMS(acc[mt*4+g*2], acc[mt*4+g*2+1], ah[mt], al[mt], bh, bl);
            }
        }
    }

    float* P = part + ((long)s*Bq + b)*Nq*Mq;
    const int erow = (lane >> 2), ecol = (lane & 3) << 1;
    #pragma unroll
    for (int mt = 0; mt < 2; mt++) {
        int r0 = m0 + mt*16 + erow;
        #pragma unroll
        for (int g = 0; g < 2; g++)
            #pragma unroll
            for (int hcol = 0; hcol < 2; hcol++) {
                int t = mt*4 + g*2 + hcol;
                int col = cg*32 + g*16 + hcol*8 + ecol;
                *(float2*)&P[r0*64 + col]     = make_float2(acc[t][0], acc[t][1]);
                *(float2*)&P[(r0+8)*64 + col] = make_float2(acc[t][2], acc[t][3]);
            }
    }
}

// ==== FUSED GRU stage: bias_msg + msg_reduce + gate GEMMs + update =========
// One CTA per batch. smem: hs[8192] ms[8192] wih[12288] whh[12288] + 128.
#define GRUF_SMEM ((8192*2 + 12288*2 + 128)*4)   /* 164352 */

__global__ __launch_bounds__(256)
void gru_fused(const float* __restrict__ part, const float* __restrict__ be3,
               const float* __restrict__ WihT, const float* __restrict__ WhhT,
               const float* __restrict__ bih, const float* __restrict__ bhh,
               const int* __restrict__ g_size,
               float* __restrict__ h, uint32* __restrict__ hp)
{
    extern __shared__ float sm[];
    float* hs   = sm;                 // [128][64]
    float* ms   = hs + 8192;          // [128][64]
    float* wih  = ms + 8192;          // [64][192]
    float* whh  = wih + 12288;        // [64][192]
    float* hsum = whh + 12288;        // [64]
    float* bm   = hsum + 64;          // [64]

    const int b = blockIdx.x;
    const int tid = threadIdx.x;

    for (int j = tid; j < 12288; j += 256) { wih[j] = WihT[j]; whh[j] = WhhT[j]; }
    for (int j = tid; j < 8192; j += 256) hs[j] = h[(long)b*8192 + j];
    __syncthreads();

    if (tid < 64) {
        float s = 0.f;
        for (int w = 0; w < 128; w++) s += hs[w*64 + tid];
        hsum[tid] = s;
    }
    __syncthreads();
    if (tid < 64) {
        float r = 0.f;
        for (int i = 0; i < 64; i++) r = fmaf(be3[tid*64+i], hsum[i], r);
        bm[tid] = r;
    }
    __syncthreads();

    for (int j = tid; j < 8192; j += 256) {
        int v = j >> 6, o = j & 63;
        float s = bm[o];
        #pragma unroll 8
        for (int sp = 0; sp < SPLITS; sp++)
            s += part[((long)sp*Bq + b)*Nq*Mq + v*64 + o];
        ms[j] = s;
    }
    __syncthreads();

    const int gs = g_size[b];
    for (int j = tid; j < 8192; j += 256) {
        int node = j >> 6, i = j & 63;
        float gr_ = bih[i],    gz = bih[64+i],  gn = bih[128+i];
        float hr  = bhh[i],    hz = bhh[64+i],  hn = bhh[128+i];
        const float* mrow = &ms[node*64];
        const float* hrow = &hs[node*64];
        #pragma unroll 4
        for (int k = 0; k < 64; k++) {
            float mv = mrow[k], hv = hrow[k];
            gr_ = fmaf(mv, wih[k*192+i],     gr_);
            gz  = fmaf(mv, wih[k*192+64+i],  gz);
            gn  = fmaf(mv, wih[k*192+128+i], gn);
            hr  = fmaf(hv, whh[k*192+i],     hr);
            hz  = fmaf(hv, whh[k*192+64+i],  hz);
            hn  = fmaf(hv, whh[k*192+128+i], hn);
        }
        float r = 1.f/(1.f+expf(-(gr_+hr)));
        float z = 1.f/(1.f+expf(-(gz+hz)));
        float n = tanhf(gn + r*hn);
        float hv2 = (1.f-z)*n + z*hrow[i];
        hv2 = (node < gs) ? hv2 : 0.f;
        long gidx = (long)b*8192 + j;
        h[gidx] = hv2;
        hp[gidx] = packsplit(hv2);
    }
}

// ---- ONE merged prep kernel (transposes, packs, init_h) --------------------
#define W3P_N (KO*64)
#define GRU_N (64*192)
#define W1_N  (256*128)
#define W2_N  (128*256)
#define IH_N  (NNODE*64)
#define PREP_TOTAL (W3P_N + GRU_N + W1_N + W2_N + IH_N)

__global__ void prep_all(const float* __restrict__ We3,
                         const float* __restrict__ Wih, const float* __restrict__ Whh,
                         const float* __restrict__ We1, const float* __restrict__ We2,
                         const float* __restrict__ h_in,
                         uint32* __restrict__ w3p,
                         float* __restrict__ WihT, float* __restrict__ WhhT,
                         uint32* __restrict__ w1p, uint32* __restrict__ w2p,
                         float* __restrict__ h, uint32* __restrict__ hp)
{
    int idx = blockIdx.x*256 + threadIdx.x;
    if (idx < W3P_N) {
        int n = idx>>6, i = idx&63;
        w3p[idx] = packsplit(We3[(long)(n>>6)*4096 + (n&63)*64 + i]);
    } else if (idx < W3P_N + GRU_N) {
        int j2 = idx - W3P_N;
        int i = j2/192, j = j2%192;
        WihT[j2] = Wih[j*64+i];
        WhhT[j2] = Whh[j*64+i];
    } else if (idx < W3P_N + GRU_N + W1_N) {
        int i = idx - W3P_N - GRU_N;
        int n = i >> 7, k = i & 127;
        w1p[i] = packsplit(We1[k*256 + n]);
    } else if (idx < W3P_N + GRU_N + W1_N + W2_N) {
        int j = idx - W3P_N - GRU_N - W1_N;
        int n = j >> 8, k = j & 255;
        w2p[j] = packsplit(We2[k*128 + n]);
    } else if (idx < PREP_TOTAL) {
        int j = idx - W3P_N - GRU_N - W1_N - W2_N;
        int node = j>>6, i = j&63;
        float v = (i<INq) ? h_in[node*INq+i] : 0.f;
        h[j] = v;
        hp[j] = packsplit(v);
    }
}

// ============ fp32 FFMA2 SGEMM body (device inline) ========================
template<int ACT, int PACKOUT>
__device__ __forceinline__
void gemm128_body(const float* __restrict__ A, const float* __restrict__ Bm,
                  const float* __restrict__ bias, void* __restrict__ Cv,
                  int Nc, int K, float As[16][132], float Bs[16][128])
{
    const int bm = blockIdx.y*128, bn = blockIdx.x*128;
    const int tid = threadIdx.x;
    const int tr = tid>>4, tc = tid&15;

    ull acc[8][4];
    #pragma unroll
    for (int i=0;i<8;i++)
        #pragma unroll
        for (int j=0;j<4;j++) acc[i][j]=0ull;

    float4 pa[2], pb[2];
    const int ntiles = K>>4;

    #pragma unroll
    for (int i=0;i<2;i++){
        int l = tid + i*256; int q = l&3, r = l>>2;
        pa[i] = *(const float4*)&A[(long)(bm+r)*K + q*4];
    }
    #pragma unroll
    for (int i=0;i<2;i++){
        int l = tid + i*256; int r = l>>5, c = (l&31)*4;
        pb[i] = *(const float4*)&Bm[(long)r*Nc + bn + c];
    }
    #pragma unroll
    for (int i=0;i<2;i++){
        int l = tid + i*256; int q = l&3, r = l>>2;
        As[q*4+0][r]=pa[i].x; As[q*4+1][r]=pa[i].y;
        As[q*4+2][r]=pa[i].z; As[q*4+3][r]=pa[i].w;
    }
    #pragma unroll
    for (int i=0;i<2;i++){
        int l = tid + i*256; int r = l>>5, c = (l&31)*4;
        *(float4*)&Bs[r][c] = pb[i];
    }
    __syncthreads();

    for (int t=0; t<ntiles; t++){
        if (t+1 < ntiles){
            int kt = (t+1)<<4;
            #pragma unroll
            for (int i=0;i<2;i++){
                int l = tid + i*256; int q = l&3, r = l>>2;
                pa[i] = *(const float4*)&A[(long)(bm+r)*K + kt + q*4];
            }
            #pragma unroll
            for (int i=0;i<2;i++){
                int l = tid + i*256; int r = l>>5, c = (l&31)*4;
                pb[i] = *(const float4*)&Bm[(long)(kt+r)*Nc + bn + c];
            }
        }
        #pragma unroll
        for (int k=0;k<16;k++){
            float4 a0 = *(const float4*)&As[k][tr*8];
            float4 a1 = *(const float4*)&As[k][tr*8+4];
            ulonglong2 bb0 = *(const ulonglong2*)&Bs[k][tc*8];
            ulonglong2 bb1 = *(const ulonglong2*)&Bs[k][tc*8+4];
            ull bp0=bb0.x, bp1=bb0.y, bp2=bb1.x, bp3=bb1.y;
            ull a2[8];
            PACK_DUP(a2[0], a0.x); PACK_DUP(a2[1], a0.y);
            PACK_DUP(a2[2], a0.z); PACK_DUP(a2[3], a0.w);
            PACK_DUP(a2[4], a1.x); PACK_DUP(a2[5], a1.y);
            PACK_DUP(a2[6], a1.z); PACK_DUP(a2[7], a1.w);
            #pragma unroll
            for (int i=0;i<8;i++){
                FMA_X2(acc[i][0], a2[i], bp0);
                FMA_X2(acc[i][1], a2[i], bp1);
                FMA_X2(acc[i][2], a2[i], bp2);
                FMA_X2(acc[i][3], a2[i], bp3);
            }
        }
        __syncthreads();
        if (t+1 < ntiles){
            #pragma unroll
            for (int i=0;i<2;i++){
                int l = tid + i*256; int q = l&3, r = l>>2;
                As[q*4+0][r]=pa[i].x; As[q*4+1][r]=pa[i].y;
                As[q*4+2][r]=pa[i].z; As[q*4+3][r]=pa[i].w;
            }
            #pragma unroll
            for (int i=0;i<2;i++){
                int l = tid + i*256; int r = l>>5, c = (l&31)*4;
                *(float4*)&Bs[r][c] = pb[i];
            }
            __syncthreads();
        }
    }

    const int gc0 = bn + tc*8;
    float bv[8];
    #pragma unroll
    for (int j=0;j<8;j++) bv[j] = bias ? bias[gc0+j] : 0.f;
    #pragma unroll
    for (int i=0;i<8;i++){
        int gr = bm + tr*8 + i;
        float o[8];
        #pragma unroll
        for (int j=0;j<4;j++){
            unsigned lo, hi;
            UNPACK2(lo, hi, acc[i][j]);
            o[2*j]   = __uint_as_float(lo) + bv[2*j];
            o[2*j+1] = __uint_as_float(hi) + bv[2*j+1];
        }
        if (ACT==1){
            #pragma unroll
            for (int j=0;j<8;j++) o[j] = fmaxf(o[j], 0.f);
        }
        if (PACKOUT==0){
            float* C = (float*)Cv;
            *(float4*)&C[(long)gr*Nc + gc0]     = make_float4(o[0],o[1],o[2],o[3]);
            *(float4*)&C[(long)gr*Nc + gc0 + 4] = make_float4(o[4],o[5],o[6],o[7]);
        } else {
            uint32* C = (uint32*)Cv;
            uint4 s0 = make_uint4(packsplit(o[0]),packsplit(o[1]),packsplit(o[2]),packsplit(o[3]));
            uint4 s1 = make_uint4(packsplit(o[4]),packsplit(o[5]),packsplit(o[6]),packsplit(o[7]));
            *(uint4*)&C[(long)gr*Nc + gc0]     = s0;
            *(uint4*)&C[(long)gr*Nc + gc0 + 4] = s1;
        }
    }
}

// dual readout GEMM: z selects (gate chain, val chain) operands; relu epilogue
__global__ __launch_bounds__(256)
void gemm128_dualro(const float* __restrict__ A0, const float* __restrict__ B0,
                    const float* __restrict__ bias0, float* __restrict__ C0, int K0,
                    const float* __restrict__ A1, const float* __restrict__ B1,
                    const float* __restrict__ bias1, float* __restrict__ C1, int K1,
                    int Nc)
{
    __shared__ __align__(16) float As[16][132];
    __shared__ __align__(16) float Bs[16][128];
    if (blockIdx.z == 0)
        gemm128_body<1,0>(A0, B0, bias0, C0, Nc, K0, As, Bs);
    else
        gemm128_body<1,0>(A1, B1, bias1, C1, Nc, K1, As, Bs);
}

// ---------------- generic tiled SGEMM body (bounds-checked) ----------------
template<int ACT>
__device__ __forceinline__
void gemm64_body(const float* __restrict__ A, const float* __restrict__ Bm,
                 const float* __restrict__ bias, float* __restrict__ C,
                 int Mr, int Nc, int K,
                 float As[16][65], float Bs[16][64])
{
    const int BM=64, BN=64, BK=16;
    int bm = blockIdx.y*BM, bn = blockIdx.x*BN;
    int tid = threadIdx.x;
    int tr = tid>>4, tc = tid&15;
    float acc[4][4] = {};
    for (int kt=0; kt<K; kt+=BK) {
        #pragma unroll
        for (int i=0;i<4;i++){
            int l = tid + i*256; int r = l>>4, c = l&15;
            int gr = bm+r, gc = kt+c;
            As[c][r] = (gr<Mr && gc<K) ? A[(long)gr*K + gc] : 0.f;
        }
        #pragma unroll
        for (int i=0;i<4;i++){
            int l = tid + i*256; int r = l>>6, c = l&63;
            int gr = kt+r, gc = bn+c;
            Bs[r][c] = (gr<K && gc<Nc) ? Bm[(long)gr*Nc + gc] : 0.f;
        }
        __syncthreads();
        #pragma unroll
        for (int k=0;k<BK;k++){
            float a[4], b[4];
            #pragma unroll
            for (int i=0;i<4;i++) a[i]=As[k][tr*4+i];
            #pragma unroll
            for (int j=0;j<4;j++) b[j]=Bs[k][tc*4+j];
            #pragma unroll
            for (int i=0;i<4;i++)
                #pragma unroll
                for (int j=0;j<4;j++) acc[i][j] = fmaf(a[i],b[j],acc[i][j]);
        }
        __syncthreads();
    }
    #pragma unroll
    for (int i=0;i<4;i++){
        int gr = bm + tr*4 + i;
        if (gr>=Mr) continue;
        #pragma unroll
        for (int j=0;j<4;j++){
            int gc = bn + tc*4 + j;
            if (gc>=Nc) continue;
            float v = acc[i][j] + (bias?bias[gc]:0.f);
            if (ACT==1) v = fmaxf(v,0.f);
            C[(long)gr*Nc + gc] = v;
        }
    }
}

// dual final readout: z0: t1@Wi3->gatel ; z1: v1@Wj3->val  (N=32, K=128)
__global__ void gemm64_dualro(const float* __restrict__ t1, const float* __restrict__ Wi3,
                              const float* __restrict__ bi3, float* __restrict__ gatel,
                              const float* __restrict__ v1, const float* __restrict__ Wj3,
                              const float* __restrict__ bj3, float* __restrict__ val)
{
    __shared__ float As[16][65];
    __shared__ float Bs[16][64];
    if (blockIdx.z == 0)
        gemm64_body<0>(t1, Wi3, bi3, gatel, NNODE, 32, 128, As, Bs);
    else
        gemm64_body<0>(v1, Wj3, bj3, val, NNODE, 32, 128, As, Bs);
}

__global__ void concat_kernel(const float* __restrict__ h, const float* __restrict__ h_in,
                              float* __restrict__ cat){
    int idx = blockIdx.x*256+threadIdx.x;
    if (idx>=NNODE*96) return;
    int node=idx/96, c=idx%96;
    cat[idx] = (c<64)? h[node*64+c] : h_in[node*INq + (c-64)];
}

__global__ void res_reduce(const float* __restrict__ gatel, const float* __restrict__ val,
                           const int* __restrict__ g_size, float* __restrict__ res){
    int t = blockIdx.x, b = blockIdx.y;
    int tid = threadIdx.x;
    int gs = g_size[b];
    float s = 0.f;
    if (tid < gs) {
        int node = b*Nq+tid;
        float gl = gatel[node*Tq+t];
        s = (1.f/(1.f+expf(-gl))) * val[node*Tq+t];
    }
    __shared__ float sm[128];
    sm[tid]=s; __syncthreads();
    for (int st=64; st>0; st>>=1){ if(tid<st) sm[tid]+=sm[tid+st]; __syncthreads(); }
    if (tid==0) res[b*Tq+t]=sm[0];
}

__global__ void logsoftmax_kernel(const float* __restrict__ res, float* __restrict__ out){
    int b = blockIdx.x; int t = threadIdx.x;
    float x = res[b*Tq+t];
    float m = x;
    for (int o=16;o>0;o>>=1) m = fmaxf(m, __shfl_xor_sync(0xffffffffu, m, o));
    float e = expf(x-m), s=e;
    for (int o=16;o>0;o>>=1) s += __shfl_xor_sync(0xffffffffu, s, o);
    out[b*Tq+t] = x - m - logf(s);
}

// ---------------------------------------------------------------------------
static inline void* symp(const void* symbol){
    void* p = nullptr;
    cudaGetSymbolAddress(&p, symbol);
    return p;
}

extern "C" void kernel_launch(void* const* d_in, const int* in_sizes, int n_in,
                              void* d_out, int out_size)
{
    const float* h_in = (const float*)d_in[0];
    const float* am   = (const float*)d_in[1];
    const int*   gsz  = (const int*)d_in[2];
    const float* We0=(const float*)d_in[3];  const float* be0=(const float*)d_in[4];
    const float* We1=(const float*)d_in[5];  const float* be1=(const float*)d_in[6];
    const float* We2=(const float*)d_in[7];  const float* be2=(const float*)d_in[8];
    const float* We3=(const float*)d_in[9];  const float* be3=(const float*)d_in[10];
    const float* Wih=(const float*)d_in[11]; const float* Whh=(const float*)d_in[12];
    const float* bih=(const float*)d_in[13]; const float* bhh=(const float*)d_in[14];
    const float* Wi0=(const float*)d_in[15]; const float* bi0=(const float*)d_in[16];
    const float* Wj0=(const float*)d_in[17]; const float* bj0=(const float*)d_in[18];
    const float* Wi1=(const float*)d_in[19]; const float* bi1=(const float*)d_in[20];
    const float* Wj1=(const float*)d_in[21]; const float* bj1=(const float*)d_in[22];
    const float* Wi2=(const float*)d_in[23]; const float* bi2=(const float*)d_in[24];
    const float* Wj2=(const float*)d_in[25]; const float* bj2=(const float*)d_in[26];
    const float* Wi3=(const float*)d_in[27]; const float* bi3=(const float*)d_in[28];
    const float* Wj3=(const float*)d_in[29]; const float* bj3=(const float*)d_in[30];
    (void)in_sizes; (void)n_in; (void)out_size;

    uint32* e256p= (uint32*)symp(d_e256p);
    uint32* fp   = (uint32*)symp(d_fp);
    uint32* w1p  = (uint32*)symp(d_w1p);
    uint32* w2p  = (uint32*)symp(d_w2p);
    uint32* w3p  = (uint32*)symp(d_w3p);
    uint32* g    = (uint32*)symp(d_g);
    float* h    = (float*)symp(d_h);
    uint32* hp   = (uint32*)symp(d_hp);
    float* part = (float*)symp(d_part);
    float* WihT = (float*)symp(d_WihT);
    float* WhhT = (float*)symp(d_WhhT);
    float* cat  = (float*)symp(d_cat);   float* t1   = (float*)symp(d_t1);
    float* t2   = (float*)symp(d_t2);    float* v1   = (float*)symp(d_v1);
    float* v2   = (float*)symp(d_v2);    float* gatel= (float*)symp(d_gatel);
    float* val  = (float*)symp(d_val);   float* res  = (float*)symp(d_res);
    float* out  = (float*)d_out;

    cudaFuncSetAttribute(mlp1_mma64,
                         cudaFuncAttributeMaxDynamicSharedMemorySize, M64_SMEM);
    cudaFuncSetAttribute(mlp2_mma64,
                         cudaFuncAttributeMaxDynamicSharedMemorySize, M64_SMEM);
    cudaFuncSetAttribute(splitk_mma,
                         cudaFuncAttributeMaxDynamicSharedMemorySize, SPLITK_SMEM);
    cudaFuncSetAttribute(gmma,
                         cudaFuncAttributeMaxDynamicSharedMemorySize, GMMA_SMEM);
    cudaFuncSetAttribute(gru_fused,
                         cudaFuncAttributeMaxDynamicSharedMemorySize, GRUF_SMEM);

    // merged prep (weight packs/transposes + init_h/hp, 1 launch)
    prep_all<<<(PREP_TOTAL+255)/256,256>>>(We3, Wih, Whh, We1, We2, h_in,
                                           w3p, WihT, WhhT, w1p, w2p, h, hp);

    // edge MLP: 4 -> 128 -> 256 -> 128 (relu each)
    mlp1_mma64<<<NE/64,256,M64_SMEM>>>(am, We0, be0, w1p, be1, e256p);
    mlp2_mma64<<<NE/64,256,M64_SMEM>>>(e256p, w2p, be2, fp);

    for (int layer=0; layer<3; layer++) {
        gmma<<<dim3(64,32),256,GMMA_SMEM>>>(hp, w3p, g);
        splitk_mma<<<dim3(SPLITS,Bq), 256, SPLITK_SMEM>>>(fp, g, part);
        gru_fused<<<Bq,256,GRUF_SMEM>>>(part, be3, WihT, WhhT, bih, bhh, gsz, h, hp);
    }

    // readout: gate & val chains fused per layer via blockIdx.z
    concat_kernel<<<768,256>>>(h, h_in, cat);
    gemm128_dualro<<<dim3(1,16,2), 256>>>(cat, Wi0, bi0, t1, 96,
                                          h,   Wj0, bj0, v1, 64, 128);
    gemm128_dualro<<<dim3(2,16,2), 256>>>(t1, Wi1, bi1, t2, 128,
                                          v1, Wj1, bj1, v2, 128, 256);
    gemm128_dualro<<<dim3(1,16,2), 256>>>(t2, Wi2, bi2, t1, 256,
                                          v2, Wj2, bj2, v1, 256, 128);
    gemm64_dualro<<<dim3(1,32,2), 256>>>(t1, Wi3, bi3, gatel,
                                         v1, Wj3, bj3, val);

    res_reduce<<<dim3(Tq,Bq),128>>>(gatel, val, gsz, res);
    logsoftmax_kernel<<<Bq,Tq>>>(res, out);
}

// round 15
// speedup vs baseline: 1.4638x; 1.4638x over previous
#include <cuda_runtime.h>
#include <cuda_bf16.h>
#include <math.h>
#include <stdint.h>

#define Bq 16
#define Nq 128
#define Hq 64
#define Mq 64
#define INq 32
#define Tq 32
#define NE (Bq*Nq*Nq)        /* 262144 edges */
#define NNODE (Bq*Nq)        /* 2048 nodes  */
#define KO 8192              /* 128*64      */
#define KBIG (Nq*128)        /* 16384       */
#define SPLITS 32
#define KS (KBIG/SPLITS)     /* 512         */

typedef unsigned long long ull;
typedef unsigned int uint32;

// ---- packed f32x2 helpers (sm_103a) ---------------------------------------
#define PACK_DUP(d, s) asm("mov.b64 %0, {%1, %1};" : "=l"(d) : "r"(__float_as_uint(s)))
#define FMA_X2(d, a, b) asm("fma.rn.f32x2 %0, %1, %2, %0;" : "+l"(d) : "l"(a), "l"(b))
#define UNPACK2(lo, hi, s) asm("mov.b64 {%0, %1}, %2;" : "=r"(lo), "=r"(hi) : "l"(s))

// ---- mma.sync / ldmatrix helpers ------------------------------------------
__device__ __forceinline__ uint32 smem_u32(const void* p) {
    uint32 a;
    asm("{ .reg .u64 t; cvta.to.shared.u64 t, %1; cvt.u32.u64 %0, t; }" : "=r"(a) : "l"(p));
    return a;
}

#define LDSM4(r0,r1,r2,r3,addr) \
    asm volatile("ldmatrix.sync.aligned.m8n8.x4.shared.b16 {%0,%1,%2,%3}, [%4];" \
        : "=r"(r0),"=r"(r1),"=r"(r2),"=r"(r3) : "r"(addr))

__device__ __forceinline__ void mma_bf16(float* c, const uint32* a, uint32 b0, uint32 b1){
    asm volatile("mma.sync.aligned.m16n8k16.row.col.f32.bf16.bf16.f32 "
        "{%0,%1,%2,%3},{%4,%5,%6,%7},{%8,%9},{%0,%1,%2,%3};"
        : "+f"(c[0]),"+f"(c[1]),"+f"(c[2]),"+f"(c[3])
        : "r"(a[0]),"r"(a[1]),"r"(a[2]),"r"(a[3]),"r"(b0),"r"(b1));
}

__device__ __forceinline__ uint32 packsplit(float v){
    __nv_bfloat16 h = __float2bfloat16(v);
    float r = v - __bfloat162float(h);
    __nv_bfloat16 l = __float2bfloat16(r);
    return (uint32)__bfloat16_as_ushort(h) | ((uint32)__bfloat16_as_ushort(l) << 16);
}

#define SPLIT8(e0,e1,e2,e3,e4,e5,e6,e7,H,L) do { \
    H.x=(e0&0xffffu)|(e1<<16); H.y=(e2&0xffffu)|(e3<<16); \
    H.z=(e4&0xffffu)|(e5<<16); H.w=(e6&0xffffu)|(e7<<16); \
    L.x=(e0>>16)|(e1&0xffff0000u); L.y=(e2>>16)|(e3&0xffff0000u); \
    L.z=(e4>>16)|(e5&0xffff0000u); L.w=(e6>>16)|(e7&0xffff0000u); \
} while(0)

#define MMA_TERMS(c0, c1, ah, al, bh, bl) do { \
    mma_bf16(c0, ah, bh[0], bh[1]); \
    mma_bf16(c0, ah, bl[0], bl[1]); \
    mma_bf16(c0, al, bh[0], bh[1]); \
    mma_bf16(c1, ah, bh[2], bh[3]); \
    mma_bf16(c1, ah, bl[2], bl[3]); \
    mma_bf16(c1, al, bh[2], bh[3]); \
} while(0)

// ---------------- scratch (static device globals; no allocation) ----------
__device__ uint32 d_e256p[(long)NE*256]; // mlp1 out, packed bf16 hi/lo
__device__ uint32 d_fp[(long)NE*128];    // edge features, packed bf16 hi/lo
__device__ uint32 d_w1p[256*128];        // W1^T packed [NOUT=256][K=128]
__device__ uint32 d_w2p[128*256];        // W2^T packed [NOUT=128][K=256]
__device__ uint32 d_w3p[KO*64];          // W3t packed [n=8192][k=64]
__device__ float d_h[NNODE*Hq];
__device__ uint32 d_hp[NNODE*Hq];        // h packed bf16 hi/lo
__device__ uint32 d_g[(long)NNODE*KO];   // g packed bf16 hi/lo
__device__ float d_part[(long)SPLITS*Bq*Nq*Mq];
__device__ float d_msg[NNODE*Mq];
__device__ float d_gi[NNODE*192];
__device__ float d_gh[NNODE*192];
__device__ float d_WihT[Hq*192];
__device__ float d_WhhT[Hq*192];
__device__ float d_bmsg[Bq*Mq];
__device__ float d_cat[NNODE*96];
__device__ float d_t1[NNODE*256];
__device__ float d_t2[NNODE*256];
__device__ float d_v1[NNODE*256];
__device__ float d_v2[NNODE*256];
__device__ float d_gatel[NNODE*Tq];
__device__ float d_val[NNODE*Tq];
__device__ float d_res[Bq*Tq];

// ==== 64-row MLP layer kernels (R8 config: 256 thr, 8 warps, 32x32 tiles) ==
#define KP64 136
#define M64_SMEM ((2*64*KP64 + 2*128*KP64)*2)   /* 104448 */

__global__ __launch_bounds__(256)
void mlp1_mma64(const float* __restrict__ am,
                const float* __restrict__ We0, const float* __restrict__ be0,
                const uint32* __restrict__ Wp, const float* __restrict__ bias,
                uint32* __restrict__ Cout)
{
    extern __shared__ __align__(16) char smem[];
    __nv_bfloat16* Ah = (__nv_bfloat16*)smem;          // [64][KP64]
    __nv_bfloat16* Al = Ah + 64*KP64;
    __nv_bfloat16* Wh = Al + 64*KP64;                  // [128][KP64]
    __nv_bfloat16* Wl = Wh + 128*KP64;

    const int tid = threadIdx.x;
    const int wid = tid >> 5, lane = tid & 31;
    const long bm = (long)blockIdx.x * 64;
    const int m0 = (wid & 1) * 32;
    const int cg = wid >> 1;                           // 4 col groups of 32

    const uint32 sAh = smem_u32(Ah), sAl = smem_u32(Al);
    const uint32 sWh = smem_u32(Wh), sWl = smem_u32(Wl);

    {
        int r = tid >> 2, seg = tid & 3;
        float4 a = *(const float4*)&am[(bm + r) * 4];
        #pragma unroll
        for (int c4 = 0; c4 < 8; c4++) {
            int c = seg*32 + c4*4;
            ull hv = 0, lv = 0;
            #pragma unroll
            for (int j = 0; j < 4; j++) {
                int n = c + j;
                float v = be0[n];
                v = fmaf(a.x, We0[n], v);
                v = fmaf(a.y, We0[128+n], v);
                v = fmaf(a.z, We0[256+n], v);
                v = fmaf(a.w, We0[384+n], v);
                v = fmaxf(v, 0.f);
                uint32 p = packsplit(v);
                hv |= ((ull)(p & 0xffffu)) << (16*j);
                lv |= ((ull)(p >> 16)) << (16*j);
            }
            *(ull*)&Ah[r*KP64 + c] = hv;
            *(ull*)&Al[r*KP64 + c] = lv;
        }
    }

    const int alrow = lane & 15;
    const uint32 a_koff = ((lane >> 4) << 3);
    const int brow = ((lane >> 4) & 1) * 8 + (lane & 7);
    const uint32 b_koff = ((lane >> 3) & 1) * 8;
    const int erow = (lane >> 2);
    const int ecol = (lane & 3) << 1;

    #pragma unroll 1
    for (int nh = 0; nh < 2; nh++) {
        __syncthreads();
        for (int gi = tid; gi < 128*16; gi += 256) {
            int n = gi >> 4, k = (gi & 15) * 8;
            const uint32* src = &Wp[(long)(nh*128 + n)*128 + k];
            uint4 v0 = *(const uint4*)src, v1 = *(const uint4*)(src+4);
            uint4 H, L;
            SPLIT8(v0.x,v0.y,v0.z,v0.w,v1.x,v1.y,v1.z,v1.w,H,L);
            *(uint4*)&Wh[n*KP64 + k] = H;
            *(uint4*)&Wl[n*KP64 + k] = L;
        }
        __syncthreads();

        float acc[8][4] = {};
        #pragma unroll
        for (int ks = 0; ks < 8; ks++) {
            const uint32 kk = ks * 16;
            uint32 ah[2][4], al[2][4];
            #pragma unroll
            for (int mt = 0; mt < 2; mt++) {
                uint32 ab = (uint32)(((m0 + mt*16 + alrow)*KP64 + kk + a_koff) << 1);
                LDSM4(ah[mt][0],ah[mt][1],ah[mt][2],ah[mt][3], sAh + ab);
                LDSM4(al[mt][0],al[mt][1],al[mt][2],al[mt][3], sAl + ab);
            }
            #pragma unroll
            for (int g = 0; g < 2; g++) {
                int n0 = cg*32 + g*16;
                uint32 bh[4], bl[4];
                uint32 bb = (uint32)(((n0 + brow)*KP64 + kk + b_koff) << 1);
                LDSM4(bh[0],bh[1],bh[2],bh[3], sWh + bb);
                LDSM4(bl[0],bl[1],bl[2],bl[3], sWl + bb);
                #pragma unroll
                for (int mt = 0; mt < 2; mt++)
                    MMA_TERMS(acc[mt*4+g*2], acc[mt*4+g*2+1], ah[mt], al[mt], bh, bl);
            }
        }
        #pragma unroll
        for (int mt = 0; mt < 2; mt++) {
            long r0 = bm + m0 + mt*16 + erow;
            #pragma unroll
            for (int g = 0; g < 2; g++)
                #pragma unroll
                for (int hcol = 0; hcol < 2; hcol++) {
                    int t = mt*4 + g*2 + hcol;
                    int col = nh*128 + cg*32 + g*16 + hcol*8 + ecol;
                    float b0 = bias[col], b1 = bias[col+1];
                    float v0 = fmaxf(acc[t][0]+b0, 0.f), v1 = fmaxf(acc[t][1]+b1, 0.f);
                    float v2 = fmaxf(acc[t][2]+b0, 0.f), v3 = fmaxf(acc[t][3]+b1, 0.f);
                    *(uint2*)&Cout[r0*256 + col]     = make_uint2(packsplit(v0), packsplit(v1));
                    *(uint2*)&Cout[(r0+8)*256 + col] = make_uint2(packsplit(v2), packsplit(v3));
                }
        }
    }
}

__global__ __launch_bounds__(256)
void mlp2_mma64(const uint32* __restrict__ Ap, const uint32* __restrict__ Wp,
                const float* __restrict__ bias, uint32* __restrict__ Cout)
{
    extern __shared__ __align__(16) char smem[];
    __nv_bfloat16* Ah = (__nv_bfloat16*)smem;          // [64][KP64]
    __nv_bfloat16* Al = Ah + 64*KP64;
    __nv_bfloat16* Wh = Al + 64*KP64;                  // [128][KP64]
    __nv_bfloat16* Wl = Wh + 128*KP64;

    const int tid = threadIdx.x;
    const int wid = tid >> 5, lane = tid & 31;
    const long bm = (long)blockIdx.x * 64;
    const int m0 = (wid & 1) * 32;
    const int cg = wid >> 1;

    const uint32 sAh = smem_u32(Ah), sAl = smem_u32(Al);
    const uint32 sWh = smem_u32(Wh), sWl = smem_u32(Wl);

    const int alrow = lane & 15;
    const uint32 a_koff = ((lane >> 4) << 3);
    const int brow = ((lane >> 4) & 1) * 8 + (lane & 7);
    const uint32 b_koff = ((lane >> 3) & 1) * 8;

    float acc[8][4] = {};

    #pragma unroll 1
    for (int ck = 0; ck < 2; ck++) {
        __syncthreads();
        for (int gi = tid; gi < 64*16; gi += 256) {
            int r = gi >> 4, k = (gi & 15) * 8;
            const uint32* src = &Ap[(bm + r)*256 + ck*128 + k];
            uint4 v0 = *(const uint4*)src, v1 = *(const uint4*)(src+4);
            uint4 H, L;
            SPLIT8(v0.x,v0.y,v0.z,v0.w,v1.x,v1.y,v1.z,v1.w,H,L);
            *(uint4*)&Ah[r*KP64 + k] = H;
            *(uint4*)&Al[r*KP64 + k] = L;
        }
        for (int gi = tid; gi < 128*16; gi += 256) {
            int n = gi >> 4, k = (gi & 15) * 8;
            const uint32* src = &Wp[(long)n*256 + ck*128 + k];
            uint4 v0 = *(const uint4*)src, v1 = *(const uint4*)(src+4);
            uint4 H, L;
            SPLIT8(v0.x,v0.y,v0.z,v0.w,v1.x,v1.y,v1.z,v1.w,H,L);
            *(uint4*)&Wh[n*KP64 + k] = H;
            *(uint4*)&Wl[n*KP64 + k] = L;
        }
        __syncthreads();

        #pragma unroll
        for (int ks = 0; ks < 8; ks++) {
            const uint32 kk = ks * 16;
            uint32 ah[2][4], al[2][4];
            #pragma unroll
            for (int mt = 0; mt < 2; mt++) {
                uint32 ab = (uint32)(((m0 + mt*16 + alrow)*KP64 + kk + a_koff) << 1);
                LDSM4(ah[mt][0],ah[mt][1],ah[mt][2],ah[mt][3], sAh + ab);
                LDSM4(al[mt][0],al[mt][1],al[mt][2],al[mt][3], sAl + ab);
            }
            #pragma unroll
            for (int g = 0; g < 2; g++) {
                int n0 = cg*32 + g*16;
                uint32 bh[4], bl[4];
                uint32 bb = (uint32)(((n0 + brow)*KP64 + kk + b_koff) << 1);
                LDSM4(bh[0],bh[1],bh[2],bh[3], sWh + bb);
                LDSM4(bl[0],bl[1],bl[2],bl[3], sWl + bb);
                #pragma unroll
                for (int mt = 0; mt < 2; mt++)
                    MMA_TERMS(acc[mt*4+g*2], acc[mt*4+g*2+1], ah[mt], al[mt], bh, bl);
            }
        }
    }

    const int erow = (lane >> 2), ecol = (lane & 3) << 1;
    #pragma unroll
    for (int mt = 0; mt < 2; mt++) {
        long r0 = bm + m0 + mt*16 + erow;
        #pragma unroll
        for (int g = 0; g < 2; g++)
            #pragma unroll
            for (int hcol = 0; hcol < 2; hcol++) {
                int t = mt*4 + g*2 + hcol;
                int col = cg*32 + g*16 + hcol*8 + ecol;
                float b0 = bias[col], b1 = bias[col+1];
                float v0 = fmaxf(acc[t][0]+b0, 0.f), v1 = fmaxf(acc[t][1]+b1, 0.f);
                float v2 = fmaxf(acc[t][2]+b0, 0.f), v3 = fmaxf(acc[t][3]+b1, 0.f);
                *(uint2*)&Cout[r0*128 + col]     = make_uint2(packsplit(v0), packsplit(v1));
                *(uint2*)&Cout[(r0+8)*128 + col] = make_uint2(packsplit(v2), packsplit(v3));
            }
    }
}

// ====== g-GEMM on tensor path: g[2048,8192] = hp[2048,64] @ w3p^T ==========
#define KPG 72
#define GMMA_SMEM ((2*64*KPG + 2*128*KPG)*2)   /* 55296 */

__global__ __launch_bounds__(256,3)
void gmma(const uint32* __restrict__ hp, const uint32* __restrict__ w3p,
          uint32* __restrict__ g)
{
    extern __shared__ __align__(16) char smem[];
    __nv_bfloat16* Ah = (__nv_bfloat16*)smem;          // [64][KPG]
    __nv_bfloat16* Al = Ah + 64*KPG;
    __nv_bfloat16* Wh = Al + 64*KPG;                   // [128][KPG]
    __nv_bfloat16* Wl = Wh + 128*KPG;

    const int tid = threadIdx.x;
    const int wid = tid >> 5, lane = tid & 31;
    const long bm = (long)blockIdx.y * 64;
    const int bn = blockIdx.x * 128;
    const int m0 = (wid & 1) * 32;
    const int cg = wid >> 1;

    const uint32 sAh = smem_u32(Ah), sAl = smem_u32(Al);
    const uint32 sWh = smem_u32(Wh), sWl = smem_u32(Wl);

    for (int gi = tid; gi < 64*8; gi += 256) {
        int r = gi >> 3, k = (gi & 7) * 8;
        const uint32* src = &hp[(bm + r)*64 + k];
        uint4 v0 = *(const uint4*)src, v1 = *(const uint4*)(src+4);
        uint4 H, L;
        SPLIT8(v0.x,v0.y,v0.z,v0.w,v1.x,v1.y,v1.z,v1.w,H,L);
        *(uint4*)&Ah[r*KPG + k] = H;
        *(uint4*)&Al[r*KPG + k] = L;
    }
    for (int gi = tid; gi < 128*8; gi += 256) {
        int n = gi >> 3, k = (gi & 7) * 8;
        const uint32* src = &w3p[(long)(bn + n)*64 + k];
        uint4 v0 = *(const uint4*)src, v1 = *(const uint4*)(src+4);
        uint4 H, L;
        SPLIT8(v0.x,v0.y,v0.z,v0.w,v1.x,v1.y,v1.z,v1.w,H,L);
        *(uint4*)&Wh[n*KPG + k] = H;
        *(uint4*)&Wl[n*KPG + k] = L;
    }
    __syncthreads();

    const int alrow = lane & 15;
    const uint32 a_koff = ((lane >> 4) << 3);
    const int brow = ((lane >> 4) & 1) * 8 + (lane & 7);
    const uint32 b_koff = ((lane >> 3) & 1) * 8;

    float acc[8][4] = {};
    #pragma unroll
    for (int ks = 0; ks < 4; ks++) {
        const uint32 kk = ks * 16;
        uint32 ah[2][4], al[2][4];
        #pragma unroll
        for (int mt = 0; mt < 2; mt++) {
            uint32 ab = (uint32)(((m0 + mt*16 + alrow)*KPG + kk + a_koff) << 1);
            LDSM4(ah[mt][0],ah[mt][1],ah[mt][2],ah[mt][3], sAh + ab);
            LDSM4(al[mt][0],al[mt][1],al[mt][2],al[mt][3], sAl + ab);
        }
        #pragma unroll
        for (int gg = 0; gg < 2; gg++) {
            int n0 = cg*32 + gg*16;
            uint32 bh[4], bl[4];
            uint32 bb = (uint32)(((n0 + brow)*KPG + kk + b_koff) << 1);
            LDSM4(bh[0],bh[1],bh[2],bh[3], sWh + bb);
            LDSM4(bl[0],bl[1],bl[2],bl[3], sWl + bb);
            #pragma unroll
            for (int mt = 0; mt < 2; mt++)
                MMA_TERMS(acc[mt*4+gg*2], acc[mt*4+gg*2+1], ah[mt], al[mt], bh, bl);
        }
    }

    const int erow = (lane >> 2), ecol = (lane & 3) << 1;
    #pragma unroll
    for (int mt = 0; mt < 2; mt++) {
        long r0 = bm + m0 + mt*16 + erow;
        #pragma unroll
        for (int gg = 0; gg < 2; gg++)
            #pragma unroll
            for (int hcol = 0; hcol < 2; hcol++) {
                int t = mt*4 + gg*2 + hcol;
                int col = bn + cg*32 + gg*16 + hcol*8 + ecol;
                *(uint2*)&g[r0*KO + col]      = make_uint2(packsplit(acc[t][0]), packsplit(acc[t][1]));
                *(uint2*)&g[(r0+8)*KO + col]  = make_uint2(packsplit(acc[t][2]), packsplit(acc[t][3]));
            }
    }
}

// ============== split-K msg contraction via mma (bf16 3-term) ==============
#define SKP 136
#define SPLITK_SMEM ((2*128*SKP + 2*64*SKP)*2)  /* 104448 */

__global__ __launch_bounds__(256)
void splitk_mma(const uint32* __restrict__ fp, const uint32* __restrict__ gp,
                float* __restrict__ part)
{
    extern __shared__ __align__(16) char smem[];
    __nv_bfloat16* Ah  = (__nv_bfloat16*)smem;          // [128][SKP]
    __nv_bfloat16* Al  = Ah + 128*SKP;
    __nv_bfloat16* Bth = Al + 128*SKP;                  // [64][SKP]
    __nv_bfloat16* Btl = Bth + 64*SKP;

    const int s = blockIdx.x, b = blockIdx.y;
    const int tid = threadIdx.x;
    const int wid = tid >> 5, lane = tid & 31;
    const int m0 = (wid & 3) * 32;
    const int cg = wid >> 2;

    const uint32 sAh = smem_u32(Ah),  sAl = smem_u32(Al);
    const uint32 sBh = smem_u32(Bth), sBl = smem_u32(Btl);

    const int alrow = lane & 15;
    const uint32 a_koff = ((lane >> 4) << 3);
    const int brow = ((lane >> 4) & 1) * 8 + (lane & 7);
    const uint32 b_koff = ((lane >> 3) & 1) * 8;

    float acc[8][4] = {};

    #pragma unroll 1
    for (int ck = 0; ck < KS/128; ck++) {
        const int k0 = s*KS + ck*128;
        if (ck > 0) __syncthreads();

        const uint32* Abase = fp + (long)b*Nq*KBIG + k0;
        for (int gi = tid; gi < 128*16; gi += 256) {
            int r = gi >> 4, k = (gi & 15) * 8;
            const uint32* src = Abase + (long)r*KBIG + k;
            uint4 v0 = *(const uint4*)src, v1 = *(const uint4*)(src+4);
            uint4 H, L;
            SPLIT8(v0.x,v0.y,v0.z,v0.w,v1.x,v1.y,v1.z,v1.w,H,L);
            *(uint4*)&Ah[r*SKP + k] = H;
            *(uint4*)&Al[r*SKP + k] = L;
        }
        const uint32* Bbase = gp + ((long)b*KBIG + k0) * 64;
        {
            int o = tid & 63, kq = (tid >> 6) * 4;
            #pragma unroll
            for (int it = 0; it < 8; it++) {
                int kk = it*16 + kq;
                uint32 p0 = Bbase[(kk+0)*64 + o];
                uint32 p1 = Bbase[(kk+1)*64 + o];
                uint32 p2 = Bbase[(kk+2)*64 + o];
                uint32 p3 = Bbase[(kk+3)*64 + o];
                ull hv = (ull)(p0&0xffffu) | ((ull)(p1&0xffffu)<<16)
                       | ((ull)(p2&0xffffu)<<32) | ((ull)(p3&0xffffu)<<48);
                ull lv = (ull)(p0>>16) | ((ull)(p1>>16)<<16)
                       | ((ull)(p2>>16)<<32) | ((ull)(p3>>16)<<48);
                *(ull*)&Bth[o*SKP + kk] = hv;
                *(ull*)&Btl[o*SKP + kk] = lv;
            }
        }
        __syncthreads();

        #pragma unroll
        for (int ks = 0; ks < 8; ks++) {
            const uint32 kk = ks * 16;
            uint32 ah[2][4], al[2][4];
            #pragma unroll
            for (int mt = 0; mt < 2; mt++) {
                uint32 ab = (uint32)(((m0 + mt*16 + alrow)*SKP + kk + a_koff) << 1);
                LDSM4(ah[mt][0],ah[mt][1],ah[mt][2],ah[mt][3], sAh + ab);
                LDSM4(al[mt][0],al[mt][1],al[mt][2],al[mt][3], sAl + ab);
            }
            #pragma unroll
            for (int g = 0; g < 2; g++) {
                int n0 = cg*32 + g*16;
                uint32 bh[4], bl[4];
                uint32 bb = (uint32)(((n0 + brow)*SKP + kk + b_koff) << 1);
                LDSM4(bh[0],bh[1],bh[2],bh[3], sBh + bb);
                LDSM4(bl[0],bl[1],bl[2],bl[3], sBl + bb);
                #pragma unroll
                for (int mt = 0; mt < 2; mt++)
                    MMA_TERMS(acc[mt*4+g*2], acc[mt*4+g*2+1], ah[mt], al[mt], bh, bl);
            }
        }
    }

    float* P = part + ((long)s*Bq + b)*Nq*Mq;
    const int erow = (lane >> 2), ecol = (lane & 3) << 1;
    #pragma unroll
    for (int mt = 0; mt < 2; mt++) {
        int r0 = m0 + mt*16 + erow;
        #pragma unroll
        for (int g = 0; g < 2; g++)
            #pragma unroll
            for (int hcol = 0; hcol < 2; hcol++) {
                int t = mt*4 + g*2 + hcol;
                int col = cg*32 + g*16 + hcol*8 + ecol;
                *(float2*)&P[r0*64 + col]     = make_float2(acc[t][0], acc[t][1]);
                *(float2*)&P[(r0+8)*64 + col] = make_float2(acc[t][2], acc[t][3]);
            }
    }
}

// ---- ONE merged prep kernel (transposes, packs, init_h) --------------------
#define W3P_N (KO*64)
#define GRU_N (64*192)
#define W1_N  (256*128)
#define W2_N  (128*256)
#define IH_N  (NNODE*64)
#define PREP_TOTAL (W3P_N + GRU_N + W1_N + W2_N + IH_N)

__global__ void prep_all(const float* __restrict__ We3,
                         const float* __restrict__ Wih, const float* __restrict__ Whh,
                         const float* __restrict__ We1, const float* __restrict__ We2,
                         const float* __restrict__ h_in,
                         uint32* __restrict__ w3p,
                         float* __restrict__ WihT, float* __restrict__ WhhT,
                         uint32* __restrict__ w1p, uint32* __restrict__ w2p,
                         float* __restrict__ h, uint32* __restrict__ hp)
{
    int idx = blockIdx.x*256 + threadIdx.x;
    if (idx < W3P_N) {
        int n = idx>>6, i = idx&63;
        w3p[idx] = packsplit(We3[(long)(n>>6)*4096 + (n&63)*64 + i]);
    } else if (idx < W3P_N + GRU_N) {
        int j2 = idx - W3P_N;
        int i = j2/192, j = j2%192;
        WihT[j2] = Wih[j*64+i];
        WhhT[j2] = Whh[j*64+i];
    } else if (idx < W3P_N + GRU_N + W1_N) {
        int i = idx - W3P_N - GRU_N;
        int n = i >> 7, k = i & 127;
        w1p[i] = packsplit(We1[k*256 + n]);
    } else if (idx < W3P_N + GRU_N + W1_N + W2_N) {
        int j = idx - W3P_N - GRU_N - W1_N;
        int n = j >> 8, k = j & 255;
        w2p[j] = packsplit(We2[k*128 + n]);
    } else if (idx < PREP_TOTAL) {
        int j = idx - W3P_N - GRU_N - W1_N - W2_N;
        int node = j>>6, i = j&63;
        float v = (i<INq) ? h_in[node*INq+i] : 0.f;
        h[j] = v;
        hp[j] = packsplit(v);
    }
}

// ============ fp32 FFMA2 SGEMM body (device inline) ========================
template<int ACT, int PACKOUT>
__device__ __forceinline__
void gemm128_body(const float* __restrict__ A, const float* __restrict__ Bm,
                  const float* __restrict__ bias, void* __restrict__ Cv,
                  int Nc, int K, float As[16][132], float Bs[16][128])
{
    const int bm = blockIdx.y*128, bn = blockIdx.x*128;
    const int tid = threadIdx.x;
    const int tr = tid>>4, tc = tid&15;

    ull acc[8][4];
    #pragma unroll
    for (int i=0;i<8;i++)
        #pragma unroll
        for (int j=0;j<4;j++) acc[i][j]=0ull;

    float4 pa[2], pb[2];
    const int ntiles = K>>4;

    #pragma unroll
    for (int i=0;i<2;i++){
        int l = tid + i*256; int q = l&3, r = l>>2;
        pa[i] = *(const float4*)&A[(long)(bm+r)*K + q*4];
    }
    #pragma unroll
    for (int i=0;i<2;i++){
        int l = tid + i*256; int r = l>>5, c = (l&31)*4;
        pb[i] = *(const float4*)&Bm[(long)r*Nc + bn + c];
    }
    #pragma unroll
    for (int i=0;i<2;i++){
        int l = tid + i*256; int q = l&3, r = l>>2;
        As[q*4+0][r]=pa[i].x; As[q*4+1][r]=pa[i].y;
        As[q*4+2][r]=pa[i].z; As[q*4+3][r]=pa[i].w;
    }
    #pragma unroll
    for (int i=0;i<2;i++){
        int l = tid + i*256; int r = l>>5, c = (l&31)*4;
        *(float4*)&Bs[r][c] = pb[i];
    }
    __syncthreads();

    for (int t=0; t<ntiles; t++){
        if (t+1 < ntiles){
            int kt = (t+1)<<4;
            #pragma unroll
            for (int i=0;i<2;i++){
                int l = tid + i*256; int q = l&3, r = l>>2;
                pa[i] = *(const float4*)&A[(long)(bm+r)*K + kt + q*4];
            }
            #pragma unroll
            for (int i=0;i<2;i++){
                int l = tid + i*256; int r = l>>5, c = (l&31)*4;
                pb[i] = *(const float4*)&Bm[(long)(kt+r)*Nc + bn + c];
            }
        }
        #pragma unroll
        for (int k=0;k<16;k++){
            float4 a0 = *(const float4*)&As[k][tr*8];
            float4 a1 = *(const float4*)&As[k][tr*8+4];
            ulonglong2 bb0 = *(const ulonglong2*)&Bs[k][tc*8];
            ulonglong2 bb1 = *(const ulonglong2*)&Bs[k][tc*8+4];
            ull bp0=bb0.x, bp1=bb0.y, bp2=bb1.x, bp3=bb1.y;
            ull a2[8];
            PACK_DUP(a2[0], a0.x); PACK_DUP(a2[1], a0.y);
            PACK_DUP(a2[2], a0.z); PACK_DUP(a2[3], a0.w);
            PACK_DUP(a2[4], a1.x); PACK_DUP(a2[5], a1.y);
            PACK_DUP(a2[6], a1.z); PACK_DUP(a2[7], a1.w);
            #pragma unroll
            for (int i=0;i<8;i++){
                FMA_X2(acc[i][0], a2[i], bp0);
                FMA_X2(acc[i][1], a2[i], bp1);
                FMA_X2(acc[i][2], a2[i], bp2);
                FMA_X2(acc[i][3], a2[i], bp3);
            }
        }
        __syncthreads();
        if (t+1 < ntiles){
            #pragma unroll
            for (int i=0;i<2;i++){
                int l = tid + i*256; int q = l&3, r = l>>2;
                As[q*4+0][r]=pa[i].x; As[q*4+1][r]=pa[i].y;
                As[q*4+2][r]=pa[i].z; As[q*4+3][r]=pa[i].w;
            }
            #pragma unroll
            for (int i=0;i<2;i++){
                int l = tid + i*256; int r = l>>5, c = (l&31)*4;
                *(float4*)&Bs[r][c] = pb[i];
            }
            __syncthreads();
        }
    }

    const int gc0 = bn + tc*8;
    float bv[8];
    #pragma unroll
    for (int j=0;j<8;j++) bv[j] = bias ? bias[gc0+j] : 0.f;
    #pragma unroll
    for (int i=0;i<8;i++){
        int gr = bm + tr*8 + i;
        float o[8];
        #pragma unroll
        for (int j=0;j<4;j++){
            unsigned lo, hi;
            UNPACK2(lo, hi, acc[i][j]);
            o[2*j]   = __uint_as_float(lo) + bv[2*j];
            o[2*j+1] = __uint_as_float(hi) + bv[2*j+1];
        }
        if (ACT==1){
            #pragma unroll
            for (int j=0;j<8;j++) o[j] = fmaxf(o[j], 0.f);
        }
        if (PACKOUT==0){
            float* C = (float*)Cv;
            *(float4*)&C[(long)gr*Nc + gc0]     = make_float4(o[0],o[1],o[2],o[3]);
            *(float4*)&C[(long)gr*Nc + gc0 + 4] = make_float4(o[4],o[5],o[6],o[7]);
        } else {
            uint32* C = (uint32*)Cv;
            uint4 s0 = make_uint4(packsplit(o[0]),packsplit(o[1]),packsplit(o[2]),packsplit(o[3]));
            uint4 s1 = make_uint4(packsplit(o[4]),packsplit(o[5]),packsplit(o[6]),packsplit(o[7]));
            *(uint4*)&C[(long)gr*Nc + gc0]     = s0;
            *(uint4*)&C[(long)gr*Nc + gc0 + 4] = s1;
        }
    }
}

// dual readout GEMM: z selects (gate chain, val chain) operands; relu epilogue
__global__ __launch_bounds__(256)
void gemm128_dualro(const float* __restrict__ A0, const float* __restrict__ B0,
                    const float* __restrict__ bias0, float* __restrict__ C0, int K0,
                    const float* __restrict__ A1, const float* __restrict__ B1,
                    const float* __restrict__ bias1, float* __restrict__ C1, int K1,
                    int Nc)
{
    __shared__ __align__(16) float As[16][132];
    __shared__ __align__(16) float Bs[16][128];
    if (blockIdx.z == 0)
        gemm128_body<1,0>(A0, B0, bias0, C0, Nc, K0, As, Bs);
    else
        gemm128_body<1,0>(A1, B1, bias1, C1, Nc, K1, As, Bs);
}

// ---------------- generic tiled SGEMM body (bounds-checked) ----------------
template<int ACT>
__device__ __forceinline__
void gemm64_body(const float* __restrict__ A, const float* __restrict__ Bm,
                 const float* __restrict__ bias, float* __restrict__ C,
                 int Mr, int Nc, int K,
                 float As[16][65], float Bs[16][64])
{
    const int BM=64, BN=64, BK=16;
    int bm = blockIdx.y*BM, bn = blockIdx.x*BN;
    int tid = threadIdx.x;
    int tr = tid>>4, tc = tid&15;
    float acc[4][4] = {};
    for (int kt=0; kt<K; kt+=BK) {
        #pragma unroll
        for (int i=0;i<4;i++){
            int l = tid + i*256; int r = l>>4, c = l&15;
            int gr = bm+r, gc = kt+c;
            As[c][r] = (gr<Mr && gc<K) ? A[(long)gr*K + gc] : 0.f;
        }
        #pragma unroll
        for (int i=0;i<4;i++){
            int l = tid + i*256; int r = l>>6, c = l&63;
            int gr = kt+r, gc = bn+c;
            Bs[r][c] = (gr<K && gc<Nc) ? Bm[(long)gr*Nc + gc] : 0.f;
        }
        __syncthreads();
        #pragma unroll
        for (int k=0;k<BK;k++){
            float a[4], b[4];
            #pragma unroll
            for (int i=0;i<4;i++) a[i]=As[k][tr*4+i];
            #pragma unroll
            for (int j=0;j<4;j++) b[j]=Bs[k][tc*4+j];
            #pragma unroll
            for (int i=0;i<4;i++)
                #pragma unroll
                for (int j=0;j<4;j++) acc[i][j] = fmaf(a[i],b[j],acc[i][j]);
        }
        __syncthreads();
    }
    #pragma unroll
    for (int i=0;i<4;i++){
        int gr = bm + tr*4 + i;
        if (gr>=Mr) continue;
        #pragma unroll
        for (int j=0;j<4;j++){
            int gc = bn + tc*4 + j;
            if (gc>=Nc) continue;
            float v = acc[i][j] + (bias?bias[gc]:0.f);
            if (ACT==1) v = fmaxf(v,0.f);
            C[(long)gr*Nc + gc] = v;
        }
    }
}

// dual final readout: z0: t1@Wi3->gatel ; z1: v1@Wj3->val  (N=32, K=128)
__global__ void gemm64_dualro(const float* __restrict__ t1, const float* __restrict__ Wi3,
                              const float* __restrict__ bi3, float* __restrict__ gatel,
                              const float* __restrict__ v1, const float* __restrict__ Wj3,
                              const float* __restrict__ bj3, float* __restrict__ val)
{
    __shared__ float As[16][65];
    __shared__ float Bs[16][64];
    if (blockIdx.z == 0)
        gemm64_body<0>(t1, Wi3, bi3, gatel, NNODE, 32, 128, As, Bs);
    else
        gemm64_body<0>(v1, Wj3, bj3, val, NNODE, 32, 128, As, Bs);
}

// dual GRU-gate GEMM: z=0 -> gi = msg@WihT + bih ; z=1 -> gh = h@WhhT + bhh
__global__ void gemm64_dual(const float* __restrict__ msg, const float* __restrict__ h,
                            const float* __restrict__ WihT, const float* __restrict__ WhhT,
                            const float* __restrict__ bih, const float* __restrict__ bhh,
                            float* __restrict__ gi, float* __restrict__ gh)
{
    const int BM=64, BN=64, BK=16;
    const int Nc = 192, K = 64;
    const float* A    = blockIdx.z ? h    : msg;
    const float* Bm   = blockIdx.z ? WhhT : WihT;
    const float* bias = blockIdx.z ? bhh  : bih;
    float* C          = blockIdx.z ? gh   : gi;

    __shared__ float As[BK][BM+1];
    __shared__ float Bs[BK][BN];
    int bm = blockIdx.y*BM, bn = blockIdx.x*BN;
    int tid = threadIdx.x;
    int tr = tid>>4, tc = tid&15;
    float acc[4][4] = {};
    for (int kt=0; kt<K; kt+=BK) {
        #pragma unroll
        for (int i=0;i<4;i++){
            int l = tid + i*256; int r = l>>4, c = l&15;
            As[c][r] = A[(long)(bm+r)*K + kt + c];
        }
        #pragma unroll
        for (int i=0;i<4;i++){
            int l = tid + i*256; int r = l>>6, c = l&63;
            int gc = bn+c;
            Bs[r][c] = (gc<Nc) ? Bm[(long)(kt+r)*Nc + gc] : 0.f;
        }
        __syncthreads();
        #pragma unroll
        for (int k=0;k<BK;k++){
            float a[4], b[4];
            #pragma unroll
            for (int i=0;i<4;i++) a[i]=As[k][tr*4+i];
            #pragma unroll
            for (int j=0;j<4;j++) b[j]=Bs[k][tc*4+j];
            #pragma unroll
            for (int i=0;i<4;i++)
                #pragma unroll
                for (int j=0;j<4;j++) acc[i][j] = fmaf(a[i],b[j],acc[i][j]);
        }
        __syncthreads();
    }
    #pragma unroll
    for (int i=0;i<4;i++){
        int gr = bm + tr*4 + i;
        #pragma unroll
        for (int j=0;j<4;j++){
            int gc = bn + tc*4 + j;
            if (gc>=Nc) continue;
            C[(long)gr*Nc + gc] = acc[i][j] + bias[gc];
        }
    }
}

__global__ void msg_reduce(const float* __restrict__ part, const float* __restrict__ bmsg,
                           float* __restrict__ msg)
{
    int idx = blockIdx.x*256 + threadIdx.x;
    if (idx >= NNODE*Mq) return;
    int node = idx>>6, o = idx&63;
    int b = node>>7, v = node&127;
    float s = bmsg[b*64+o];
    #pragma unroll 8
    for (int sp=0; sp<SPLITS; sp++)
        s += part[((long)sp*Bq + b)*Nq*Mq + v*64 + o];
    msg[idx]=s;
}

__global__ void bias_msg_kernel(const float* __restrict__ h, const float* __restrict__ be3,
                                float* __restrict__ bmsg)
{
    int b = blockIdx.x;
    __shared__ float hs[64];
    int t = threadIdx.x;
    float s = 0.f;
    for (int w=0; w<Nq; w++) s += h[((long)b*Nq+w)*64 + t];
    hs[t] = s;
    __syncthreads();
    float r = 0.f;
    for (int i=0;i<64;i++) r = fmaf(be3[t*64+i], hs[i], r);
    bmsg[b*64+t] = r;
}

__global__ void gru_update(const float* __restrict__ gi, const float* __restrict__ gh,
                           const int* __restrict__ g_size, float* __restrict__ h,
                           uint32* __restrict__ hp){
    int idx = blockIdx.x*256+threadIdx.x;
    if (idx>=NNODE*64) return;
    int node = idx>>6, i = idx&63;
    int b = node>>7, v = node&127;
    float r = 1.f/(1.f+expf(-(gi[node*192+i]     + gh[node*192+i])));
    float z = 1.f/(1.f+expf(-(gi[node*192+64+i]  + gh[node*192+64+i])));
    float n = tanhf(gi[node*192+128+i] + r*gh[node*192+128+i]);
    float hv = (1.f-z)*n + z*h[idx];
    hv = (v < g_size[b]) ? hv : 0.f;
    h[idx] = hv;
    hp[idx] = packsplit(hv);
}

__global__ void concat_kernel(const float* __restrict__ h, const float* __restrict__ h_in,
                              float* __restrict__ cat){
    int idx = blockIdx.x*256+threadIdx.x;
    if (idx>=NNODE*96) return;
    int node=idx/96, c=idx%96;
    cat[idx] = (c<64)? h[node*64+c] : h_in[node*INq + (c-64)];
}

__global__ void res_reduce(const float* __restrict__ gatel, const float* __restrict__ val,
                           const int* __restrict__ g_size, float* __restrict__ res){
    int t = blockIdx.x, b = blockIdx.y;
    int tid = threadIdx.x;
    int gs = g_size[b];
    float s = 0.f;
    if (tid < gs) {
        int node = b*Nq+tid;
        float gl = gatel[node*Tq+t];
        s = (1.f/(1.f+expf(-gl))) * val[node*Tq+t];
    }
    __shared__ float sm[128];
    sm[tid]=s; __syncthreads();
    for (int st=64; st>0; st>>=1){ if(tid<st) sm[tid]+=sm[tid+st]; __syncthreads(); }
    if (tid==0) res[b*Tq+t]=sm[0];
}

__global__ void logsoftmax_kernel(const float* __restrict__ res, float* __restrict__ out){
    int b = blockIdx.x; int t = threadIdx.x;
    float x = res[b*Tq+t];
    float m = x;
    for (int o=16;o>0;o>>=1) m = fmaxf(m, __shfl_xor_sync(0xffffffffu, m, o));
    float e = expf(x-m), s=e;
    for (int o=16;o>0;o>>=1) s += __shfl_xor_sync(0xffffffffu, s, o);
    out[b*Tq+t] = x - m - logf(s);
}

// ---------------------------------------------------------------------------
static inline void* symp(const void* symbol){
    void* p = nullptr;
    cudaGetSymbolAddress(&p, symbol);
    return p;
}

extern "C" void kernel_launch(void* const* d_in, const int* in_sizes, int n_in,
                              void* d_out, int out_size)
{
    const float* h_in = (const float*)d_in[0];
    const float* am   = (const float*)d_in[1];
    const int*   gsz  = (const int*)d_in[2];
    const float* We0=(const float*)d_in[3];  const float* be0=(const float*)d_in[4];
    const float* We1=(const float*)d_in[5];  const float* be1=(const float*)d_in[6];
    const float* We2=(const float*)d_in[7];  const float* be2=(const float*)d_in[8];
    const float* We3=(const float*)d_in[9];  const float* be3=(const float*)d_in[10];
    const float* Wih=(const float*)d_in[11]; const float* Whh=(const float*)d_in[12];
    const float* bih=(const float*)d_in[13]; const float* bhh=(const float*)d_in[14];
    const float* Wi0=(const float*)d_in[15]; const float* bi0=(const float*)d_in[16];
    const float* Wj0=(const float*)d_in[17]; const float* bj0=(const float*)d_in[18];
    const float* Wi1=(const float*)d_in[19]; const float* bi1=(const float*)d_in[20];
    const float* Wj1=(const float*)d_in[21]; const float* bj1=(const float*)d_in[22];
    const float* Wi2=(const float*)d_in[23]; const float* bi2=(const float*)d_in[24];
    const float* Wj2=(const float*)d_in[25]; const float* bj2=(const float*)d_in[26];
    const float* Wi3=(const float*)d_in[27]; const float* bi3=(const float*)d_in[28];
    const float* Wj3=(const float*)d_in[29]; const float* bj3=(const float*)d_in[30];
    (void)in_sizes; (void)n_in; (void)out_size;

    uint32* e256p= (uint32*)symp(d_e256p);
    uint32* fp   = (uint32*)symp(d_fp);
    uint32* w1p  = (uint32*)symp(d_w1p);
    uint32* w2p  = (uint32*)symp(d_w2p);
    uint32* w3p  = (uint32*)symp(d_w3p);
    uint32* g    = (uint32*)symp(d_g);
    float* h    = (float*)symp(d_h);
    uint32* hp   = (uint32*)symp(d_hp);
    float* part = (float*)symp(d_part);  float* msg  = (float*)symp(d_msg);
    float* gi   = (float*)symp(d_gi);    float* gh   = (float*)symp(d_gh);
    float* WihT = (float*)symp(d_WihT);
    float* WhhT = (float*)symp(d_WhhT);  float* bmsg = (float*)symp(d_bmsg);
    float* cat  = (float*)symp(d_cat);   float* t1   = (float*)symp(d_t1);
    float* t2   = (float*)symp(d_t2);    float* v1   = (float*)symp(d_v1);
    float* v2   = (float*)symp(d_v2);    float* gatel= (float*)symp(d_gatel);
    float* val  = (float*)symp(d_val);   float* res  = (float*)symp(d_res);
    float* out  = (float*)d_out;

    cudaFuncSetAttribute(mlp1_mma64,
                         cudaFuncAttributeMaxDynamicSharedMemorySize, M64_SMEM);
    cudaFuncSetAttribute(mlp2_mma64,
                         cudaFuncAttributeMaxDynamicSharedMemorySize, M64_SMEM);
    cudaFuncSetAttribute(splitk_mma,
                         cudaFuncAttributeMaxDynamicSharedMemorySize, SPLITK_SMEM);
    cudaFuncSetAttribute(gmma,
                         cudaFuncAttributeMaxDynamicSharedMemorySize, GMMA_SMEM);

    // merged prep (weight packs/transposes + init_h/hp, 1 launch)
    prep_all<<<(PREP_TOTAL+255)/256,256>>>(We3, Wih, Whh, We1, We2, h_in,
                                           w3p, WihT, WhhT, w1p, w2p, h, hp);

    // edge MLP: 4 -> 128 -> 256 -> 128 (relu each)
    mlp1_mma64<<<NE/64,256,M64_SMEM>>>(am, We0, be0, w1p, be1, e256p);
    mlp2_mma64<<<NE/64,256,M64_SMEM>>>(e256p, w2p, be2, fp);

    for (int layer=0; layer<3; layer++) {
        gmma<<<dim3(64,32),256,GMMA_SMEM>>>(hp, w3p, g);
        bias_msg_kernel<<<Bq,64>>>(h, be3, bmsg);
        splitk_mma<<<dim3(SPLITS,Bq), 256, SPLITK_SMEM>>>(fp, g, part);
        msg_reduce<<<512,256>>>(part, bmsg, msg);
        gemm64_dual<<<dim3(3,32,2), 256>>>(msg, h, WihT, WhhT, bih, bhh, gi, gh);
        gru_update<<<512,256>>>(gi, gh, gsz, h, hp);
    }

    // readout: gate & val chains fused per layer via blockIdx.z
    concat_kernel<<<768,256>>>(h, h_in, cat);
    gemm128_dualro<<<dim3(1,16,2), 256>>>(cat, Wi0, bi0, t1, 96,
                                          h,   Wj0, bj0, v1, 64, 128);
    gemm128_dualro<<<dim3(2,16,2), 256>>>(t1, Wi1, bi1, t2, 128,
                                          v1, Wj1, bj1, v2, 128, 256);
    gemm128_dualro<<<dim3(1,16,2), 256>>>(t2, Wi2, bi2, t1, 256,
                                          v2, Wj2, bj2, v1, 256, 128);
    gemm64_dualro<<<dim3(1,32,2), 256>>>(t1, Wi3, bi3, gatel,
                                         v1, Wj3, bj3, val);

    res_reduce<<<dim3(Tq,Bq),128>>>(gatel, val, gsz, res);
    logsoftmax_kernel<<<Bq,Tq>>>(res, out);
}

// round 16
// speedup vs baseline: 1.4775x; 1.0094x over previous
#include <cuda_runtime.h>
#include <cuda_bf16.h>
#include <math.h>
#include <stdint.h>

#define Bq 16
#define Nq 128
#define Hq 64
#define Mq 64
#define INq 32
#define Tq 32
#define NE (Bq*Nq*Nq)        /* 262144 edges */
#define NNODE (Bq*Nq)        /* 2048 nodes  */
#define KO 8192              /* 128*64      */
#define KBIG (Nq*128)        /* 16384       */
#define SPLITS 32
#define KS (KBIG/SPLITS)     /* 512         */

typedef unsigned long long ull;
typedef unsigned int uint32;

// ---- packed f32x2 helpers (sm_103a) ---------------------------------------
#define PACK_DUP(d, s) asm("mov.b64 %0, {%1, %1};" : "=l"(d) : "r"(__float_as_uint(s)))
#define FMA_X2(d, a, b) asm("fma.rn.f32x2 %0, %1, %2, %0;" : "+l"(d) : "l"(a), "l"(b))
#define UNPACK2(lo, hi, s) asm("mov.b64 {%0, %1}, %2;" : "=r"(lo), "=r"(hi) : "l"(s))

// ---- mma.sync / ldmatrix helpers ------------------------------------------
__device__ __forceinline__ uint32 smem_u32(const void* p) {
    uint32 a;
    asm("{ .reg .u64 t; cvta.to.shared.u64 t, %1; cvt.u32.u64 %0, t; }" : "=r"(a) : "l"(p));
    return a;
}

#define LDSM4(r0,r1,r2,r3,addr) \
    asm volatile("ldmatrix.sync.aligned.m8n8.x4.shared.b16 {%0,%1,%2,%3}, [%4];" \
        : "=r"(r0),"=r"(r1),"=r"(r2),"=r"(r3) : "r"(addr))

__device__ __forceinline__ void mma_bf16(float* c, const uint32* a, uint32 b0, uint32 b1){
    asm volatile("mma.sync.aligned.m16n8k16.row.col.f32.bf16.bf16.f32 "
        "{%0,%1,%2,%3},{%4,%5,%6,%7},{%8,%9},{%0,%1,%2,%3};"
        : "+f"(c[0]),"+f"(c[1]),"+f"(c[2]),"+f"(c[3])
        : "r"(a[0]),"r"(a[1]),"r"(a[2]),"r"(a[3]),"r"(b0),"r"(b1));
}

__device__ __forceinline__ uint32 packsplit(float v){
    __nv_bfloat16 h = __float2bfloat16(v);
    float r = v - __bfloat162float(h);
    __nv_bfloat16 l = __float2bfloat16(r);
    return (uint32)__bfloat16_as_ushort(h) | ((uint32)__bfloat16_as_ushort(l) << 16);
}

#define SPLIT8(e0,e1,e2,e3,e4,e5,e6,e7,H,L) do { \
    H.x=(e0&0xffffu)|(e1<<16); H.y=(e2&0xffffu)|(e3<<16); \
    H.z=(e4&0xffffu)|(e5<<16); H.w=(e6&0xffffu)|(e7<<16); \
    L.x=(e0>>16)|(e1&0xffff0000u); L.y=(e2>>16)|(e3&0xffff0000u); \
    L.z=(e4>>16)|(e5&0xffff0000u); L.w=(e6>>16)|(e7&0xffff0000u); \
} while(0)

#define MMA_TERMS(c0, c1, ah, al, bh, bl) do { \
    mma_bf16(c0, ah, bh[0], bh[1]); \
    mma_bf16(c0, ah, bl[0], bl[1]); \
    mma_bf16(c0, al, bh[0], bh[1]); \
    mma_bf16(c1, ah, bh[2], bh[3]); \
    mma_bf16(c1, ah, bl[2], bl[3]); \
    mma_bf16(c1, al, bh[2], bh[3]); \
} while(0)

// ---------------- scratch (static device globals; no allocation) ----------
__device__ uint32 d_e256p[(long)NE*256]; // mlp1 out, packed bf16 hi/lo
__device__ uint32 d_fp[(long)NE*128];    // edge features, packed bf16 hi/lo
__device__ uint32 d_w1p[256*128];        // W1^T packed [NOUT=256][K=128]
__device__ uint32 d_w2p[128*256];        // W2^T packed [NOUT=128][K=256]
__device__ uint32 d_w3p[KO*64];          // W3t packed [n=8192][k=64]
__device__ float d_h[NNODE*Hq];
__device__ uint32 d_hp[NNODE*Hq];        // h packed bf16 hi/lo
__device__ uint32 d_g[(long)NNODE*KO];   // g packed bf16 hi/lo
__device__ float d_part[(long)SPLITS*Bq*Nq*Mq];
__device__ float d_msg[NNODE*Mq];
__device__ float d_gi[NNODE*192];
__device__ float d_gh[NNODE*192];
__device__ float d_WihT[Hq*192];
__device__ float d_WhhT[Hq*192];
__device__ float d_bmsg[Bq*Mq];
__device__ float d_cat[NNODE*96];
__device__ float d_t1[NNODE*256];
__device__ float d_t2[NNODE*256];
__device__ float d_v1[NNODE*256];
__device__ float d_v2[NNODE*256];
__device__ float d_gatel[NNODE*Tq];
__device__ float d_val[NNODE*Tq];
__device__ float d_res[Bq*Tq];

// ==== 64-row MLP layer kernels (R8 config: 256 thr, 8 warps, 32x32 tiles) ==
#define KP64 136
#define M64_SMEM ((2*64*KP64 + 2*128*KP64)*2)   /* 104448 */

__global__ __launch_bounds__(256)
void mlp1_mma64(const float* __restrict__ am,
                const float* __restrict__ We0, const float* __restrict__ be0,
                const uint32* __restrict__ Wp, const float* __restrict__ bias,
                uint32* __restrict__ Cout)
{
    extern __shared__ __align__(16) char smem[];
    __nv_bfloat16* Ah = (__nv_bfloat16*)smem;          // [64][KP64]
    __nv_bfloat16* Al = Ah + 64*KP64;
    __nv_bfloat16* Wh = Al + 64*KP64;                  // [128][KP64]
    __nv_bfloat16* Wl = Wh + 128*KP64;

    const int tid = threadIdx.x;
    const int wid = tid >> 5, lane = tid & 31;
    const long bm = (long)blockIdx.x * 64;
    const int m0 = (wid & 1) * 32;
    const int cg = wid >> 1;                           // 4 col groups of 32

    const uint32 sAh = smem_u32(Ah), sAl = smem_u32(Al);
    const uint32 sWh = smem_u32(Wh), sWl = smem_u32(Wl);

    {
        int r = tid >> 2, seg = tid & 3;
        float4 a = *(const float4*)&am[(bm + r) * 4];
        #pragma unroll
        for (int c4 = 0; c4 < 8; c4++) {
            int c = seg*32 + c4*4;
            ull hv = 0, lv = 0;
            #pragma unroll
            for (int j = 0; j < 4; j++) {
                int n = c + j;
                float v = be0[n];
                v = fmaf(a.x, We0[n], v);
                v = fmaf(a.y, We0[128+n], v);
                v = fmaf(a.z, We0[256+n], v);
                v = fmaf(a.w, We0[384+n], v);
                v = fmaxf(v, 0.f);
                uint32 p = packsplit(v);
                hv |= ((ull)(p & 0xffffu)) << (16*j);
                lv |= ((ull)(p >> 16)) << (16*j);
            }
            *(ull*)&Ah[r*KP64 + c] = hv;
            *(ull*)&Al[r*KP64 + c] = lv;
        }
    }

    const int alrow = lane & 15;
    const uint32 a_koff = ((lane >> 4) << 3);
    const int brow = ((lane >> 4) & 1) * 8 + (lane & 7);
    const uint32 b_koff = ((lane >> 3) & 1) * 8;
    const int erow = (lane >> 2);
    const int ecol = (lane & 3) << 1;

    #pragma unroll 1
    for (int nh = 0; nh < 2; nh++) {
        __syncthreads();
        for (int gi = tid; gi < 128*16; gi += 256) {
            int n = gi >> 4, k = (gi & 15) * 8;
            const uint32* src = &Wp[(long)(nh*128 + n)*128 + k];
            uint4 v0 = *(const uint4*)src, v1 = *(const uint4*)(src+4);
            uint4 H, L;
            SPLIT8(v0.x,v0.y,v0.z,v0.w,v1.x,v1.y,v1.z,v1.w,H,L);
            *(uint4*)&Wh[n*KP64 + k] = H;
            *(uint4*)&Wl[n*KP64 + k] = L;
        }
        __syncthreads();

        float acc[8][4] = {};
        #pragma unroll
        for (int ks = 0; ks < 8; ks++) {
            const uint32 kk = ks * 16;
            uint32 ah[2][4], al[2][4];
            #pragma unroll
            for (int mt = 0; mt < 2; mt++) {
                uint32 ab = (uint32)(((m0 + mt*16 + alrow)*KP64 + kk + a_koff) << 1);
                LDSM4(ah[mt][0],ah[mt][1],ah[mt][2],ah[mt][3], sAh + ab);
                LDSM4(al[mt][0],al[mt][1],al[mt][2],al[mt][3], sAl + ab);
            }
            #pragma unroll
            for (int g = 0; g < 2; g++) {
                int n0 = cg*32 + g*16;
                uint32 bh[4], bl[4];
                uint32 bb = (uint32)(((n0 + brow)*KP64 + kk + b_koff) << 1);
                LDSM4(bh[0],bh[1],bh[2],bh[3], sWh + bb);
                LDSM4(bl[0],bl[1],bl[2],bl[3], sWl + bb);
                #pragma unroll
                for (int mt = 0; mt < 2; mt++)
                    MMA_TERMS(acc[mt*4+g*2], acc[mt*4+g*2+1], ah[mt], al[mt], bh, bl);
            }
        }
        #pragma unroll
        for (int mt = 0; mt < 2; mt++) {
            long r0 = bm + m0 + mt*16 + erow;
            #pragma unroll
            for (int g = 0; g < 2; g++)
                #pragma unroll
                for (int hcol = 0; hcol < 2; hcol++) {
                    int t = mt*4 + g*2 + hcol;
                    int col = nh*128 + cg*32 + g*16 + hcol*8 + ecol;
                    float b0 = bias[col], b1 = bias[col+1];
                    float v0 = fmaxf(acc[t][0]+b0, 0.f), v1 = fmaxf(acc[t][1]+b1, 0.f);
                    float v2 = fmaxf(acc[t][2]+b0, 0.f), v3 = fmaxf(acc[t][3]+b1, 0.f);
                    *(uint2*)&Cout[r0*256 + col]     = make_uint2(packsplit(v0), packsplit(v1));
                    *(uint2*)&Cout[(r0+8)*256 + col] = make_uint2(packsplit(v2), packsplit(v3));
                }
        }
    }
}

__global__ __launch_bounds__(256)
void mlp2_mma64(const uint32* __restrict__ Ap, const uint32* __restrict__ Wp,
                const float* __restrict__ bias, uint32* __restrict__ Cout)
{
    extern __shared__ __align__(16) char smem[];
    __nv_bfloat16* Ah = (__nv_bfloat16*)smem;          // [64][KP64]
    __nv_bfloat16* Al = Ah + 64*KP64;
    __nv_bfloat16* Wh = Al + 64*KP64;                  // [128][KP64]
    __nv_bfloat16* Wl = Wh + 128*KP64;

    const int tid = threadIdx.x;
    const int wid = tid >> 5, lane = tid & 31;
    const long bm = (long)blockIdx.x * 64;
    const int m0 = (wid & 1) * 32;
    const int cg = wid >> 1;

    const uint32 sAh = smem_u32(Ah), sAl = smem_u32(Al);
    const uint32 sWh = smem_u32(Wh), sWl = smem_u32(Wl);

    const int alrow = lane & 15;
    const uint32 a_koff = ((lane >> 4) << 3);
    const int brow = ((lane >> 4) & 1) * 8 + (lane & 7);
    const uint32 b_koff = ((lane >> 3) & 1) * 8;

    float acc[8][4] = {};

    #pragma unroll 1
    for (int ck = 0; ck < 2; ck++) {
        __syncthreads();
        for (int gi = tid; gi < 64*16; gi += 256) {
            int r = gi >> 4, k = (gi & 15) * 8;
            const uint32* src = &Ap[(bm + r)*256 + ck*128 + k];
            uint4 v0 = *(const uint4*)src, v1 = *(const uint4*)(src+4);
            uint4 H, L;
            SPLIT8(v0.x,v0.y,v0.z,v0.w,v1.x,v1.y,v1.z,v1.w,H,L);
            *(uint4*)&Ah[r*KP64 + k] = H;
            *(uint4*)&Al[r*KP64 + k] = L;
        }
        for (int gi = tid; gi < 128*16; gi += 256) {
            int n = gi >> 4, k = (gi & 15) * 8;
            const uint32* src = &Wp[(long)n*256 + ck*128 + k];
            uint4 v0 = *(const uint4*)src, v1 = *(const uint4*)(src+4);
            uint4 H, L;
            SPLIT8(v0.x,v0.y,v0.z,v0.w,v1.x,v1.y,v1.z,v1.w,H,L);
            *(uint4*)&Wh[n*KP64 + k] = H;
            *(uint4*)&Wl[n*KP64 + k] = L;
        }
        __syncthreads();

        #pragma unroll
        for (int ks = 0; ks < 8; ks++) {
            const uint32 kk = ks * 16;
            uint32 ah[2][4], al[2][4];
            #pragma unroll
            for (int mt = 0; mt < 2; mt++) {
                uint32 ab = (uint32)(((m0 + mt*16 + alrow)*KP64 + kk + a_koff) << 1);
                LDSM4(ah[mt][0],ah[mt][1],ah[mt][2],ah[mt][3], sAh + ab);
                LDSM4(al[mt][0],al[mt][1],al[mt][2],al[mt][3], sAl + ab);
            }
            #pragma unroll
            for (int g = 0; g < 2; g++) {
                int n0 = cg*32 + g*16;
                uint32 bh[4], bl[4];
                uint32 bb = (uint32)(((n0 + brow)*KP64 + kk + b_koff) << 1);
                LDSM4(bh[0],bh[1],bh[2],bh[3], sWh + bb);
                LDSM4(bl[0],bl[1],bl[2],bl[3], sWl + bb);
                #pragma unroll
                for (int mt = 0; mt < 2; mt++)
                    MMA_TERMS(acc[mt*4+g*2], acc[mt*4+g*2+1], ah[mt], al[mt], bh, bl);
            }
        }
    }

    const int erow = (lane >> 2), ecol = (lane & 3) << 1;
    #pragma unroll
    for (int mt = 0; mt < 2; mt++) {
        long r0 = bm + m0 + mt*16 + erow;
        #pragma unroll
        for (int g = 0; g < 2; g++)
            #pragma unroll
            for (int hcol = 0; hcol < 2; hcol++) {
                int t = mt*4 + g*2 + hcol;
                int col = cg*32 + g*16 + hcol*8 + ecol;
                float b0 = bias[col], b1 = bias[col+1];
                float v0 = fmaxf(acc[t][0]+b0, 0.f), v1 = fmaxf(acc[t][1]+b1, 0.f);
                float v2 = fmaxf(acc[t][2]+b0, 0.f), v3 = fmaxf(acc[t][3]+b1, 0.f);
                *(uint2*)&Cout[r0*128 + col]     = make_uint2(packsplit(v0), packsplit(v1));
                *(uint2*)&Cout[(r0+8)*128 + col] = make_uint2(packsplit(v2), packsplit(v3));
            }
    }
}

// ====== g-GEMM on tensor path: g[2048,8192] = hp[2048,64] @ w3p^T ==========
#define KPG 72
#define GMMA_SMEM ((2*64*KPG + 2*128*KPG)*2)   /* 55296 */

__global__ __launch_bounds__(256,3)
void gmma(const uint32* __restrict__ hp, const uint32* __restrict__ w3p,
          uint32* __restrict__ g)
{
    extern __shared__ __align__(16) char smem[];
    __nv_bfloat16* Ah = (__nv_bfloat16*)smem;          // [64][KPG]
    __nv_bfloat16* Al = Ah + 64*KPG;
    __nv_bfloat16* Wh = Al + 64*KPG;                   // [128][KPG]
    __nv_bfloat16* Wl = Wh + 128*KPG;

    const int tid = threadIdx.x;
    const int wid = tid >> 5, lane = tid & 31;
    const long bm = (long)blockIdx.y * 64;
    const int bn = blockIdx.x * 128;
    const int m0 = (wid & 1) * 32;
    const int cg = wid >> 1;

    const uint32 sAh = smem_u32(Ah), sAl = smem_u32(Al);
    const uint32 sWh = smem_u32(Wh), sWl = smem_u32(Wl);

    for (int gi = tid; gi < 64*8; gi += 256) {
        int r = gi >> 3, k = (gi & 7) * 8;
        const uint32* src = &hp[(bm + r)*64 + k];
        uint4 v0 = *(const uint4*)src, v1 = *(const uint4*)(src+4);
        uint4 H, L;
        SPLIT8(v0.x,v0.y,v0.z,v0.w,v1.x,v1.y,v1.z,v1.w,H,L);
        *(uint4*)&Ah[r*KPG + k] = H;
        *(uint4*)&Al[r*KPG + k] = L;
    }
    for (int gi = tid; gi < 128*8; gi += 256) {
        int n = gi >> 3, k = (gi & 7) * 8;
        const uint32* src = &w3p[(long)(bn + n)*64 + k];
        uint4 v0 = *(const uint4*)src, v1 = *(const uint4*)(src+4);
        uint4 H, L;
        SPLIT8(v0.x,v0.y,v0.z,v0.w,v1.x,v1.y,v1.z,v1.w,H,L);
        *(uint4*)&Wh[n*KPG + k] = H;
        *(uint4*)&Wl[n*KPG + k] = L;
    }
    __syncthreads();

    const int alrow = lane & 15;
    const uint32 a_koff = ((lane >> 4) << 3);
    const int brow = ((lane >> 4) & 1) * 8 + (lane & 7);
    const uint32 b_koff = ((lane >> 3) & 1) * 8;

    float acc[8][4] = {};
    #pragma unroll
    for (int ks = 0; ks < 4; ks++) {
        const uint32 kk = ks * 16;
        uint32 ah[2][4], al[2][4];
        #pragma unroll
        for (int mt = 0; mt < 2; mt++) {
            uint32 ab = (uint32)(((m0 + mt*16 + alrow)*KPG + kk + a_koff) << 1);
            LDSM4(ah[mt][0],ah[mt][1],ah[mt][2],ah[mt][3], sAh + ab);
            LDSM4(al[mt][0],al[mt][1],al[mt][2],al[mt][3], sAl + ab);
        }
        #pragma unroll
        for (int gg = 0; gg < 2; gg++) {
            int n0 = cg*32 + gg*16;
            uint32 bh[4], bl[4];
            uint32 bb = (uint32)(((n0 + brow)*KPG + kk + b_koff) << 1);
            LDSM4(bh[0],bh[1],bh[2],bh[3], sWh + bb);
            LDSM4(bl[0],bl[1],bl[2],bl[3], sWl + bb);
            #pragma unroll
            for (int mt = 0; mt < 2; mt++)
                MMA_TERMS(acc[mt*4+gg*2], acc[mt*4+gg*2+1], ah[mt], al[mt], bh, bl);
        }
    }

    const int erow = (lane >> 2), ecol = (lane & 3) << 1;
    #pragma unroll
    for (int mt = 0; mt < 2; mt++) {
        long r0 = bm + m0 + mt*16 + erow;
        #pragma unroll
        for (int gg = 0; gg < 2; gg++)
            #pragma unroll
            for (int hcol = 0; hcol < 2; hcol++) {
                int t = mt*4 + gg*2 + hcol;
                int col = bn + cg*32 + gg*16 + hcol*8 + ecol;
                *(uint2*)&g[r0*KO + col]      = make_uint2(packsplit(acc[t][0]), packsplit(acc[t][1]));
                *(uint2*)&g[(r0+8)*KO + col]  = make_uint2(packsplit(acc[t][2]), packsplit(acc[t][3]));
            }
    }
}

// ============== split-K msg contraction via mma (bf16 3-term) ==============
#define SKP 136
#define SPLITK_SMEM ((2*128*SKP + 2*64*SKP)*2)  /* 104448 */

__global__ __launch_bounds__(256)
void splitk_mma(const uint32* __restrict__ fp, const uint32* __restrict__ gp,
                float* __restrict__ part)
{
    extern __shared__ __align__(16) char smem[];
    __nv_bfloat16* Ah  = (__nv_bfloat16*)smem;          // [128][SKP]
    __nv_bfloat16* Al  = Ah + 128*SKP;
    __nv_bfloat16* Bth = Al + 128*SKP;                  // [64][SKP]
    __nv_bfloat16* Btl = Bth + 64*SKP;

    const int s = blockIdx.x, b = blockIdx.y;
    const int tid = threadIdx.x;
    const int wid = tid >> 5, lane = tid & 31;
    const int m0 = (wid & 3) * 32;
    const int cg = wid >> 2;

    const uint32 sAh = smem_u32(Ah),  sAl = smem_u32(Al);
    const uint32 sBh = smem_u32(Bth), sBl = smem_u32(Btl);

    const int alrow = lane & 15;
    const uint32 a_koff = ((lane >> 4) << 3);
    const int brow = ((lane >> 4) & 1) * 8 + (lane & 7);
    const uint32 b_koff = ((lane >> 3) & 1) * 8;

    float acc[8][4] = {};

    #pragma unroll 1
    for (int ck = 0; ck < KS/128; ck++) {
        const int k0 = s*KS + ck*128;
        if (ck > 0) __syncthreads();

        const uint32* Abase = fp + (long)b*Nq*KBIG + k0;
        for (int gi = tid; gi < 128*16; gi += 256) {
            int r = gi >> 4, k = (gi & 15) * 8;
            const uint32* src = Abase + (long)r*KBIG + k;
            uint4 v0 = *(const uint4*)src, v1 = *(const uint4*)(src+4);
            uint4 H, L;
            SPLIT8(v0.x,v0.y,v0.z,v0.w,v1.x,v1.y,v1.z,v1.w,H,L);
            *(uint4*)&Ah[r*SKP + k] = H;
            *(uint4*)&Al[r*SKP + k] = L;
        }
        const uint32* Bbase = gp + ((long)b*KBIG + k0) * 64;
        {
            int o = tid & 63, kq = (tid >> 6) * 4;
            #pragma unroll
            for (int it = 0; it < 8; it++) {
                int kk = it*16 + kq;
                uint32 p0 = Bbase[(kk+0)*64 + o];
                uint32 p1 = Bbase[(kk+1)*64 + o];
                uint32 p2 = Bbase[(kk+2)*64 + o];
                uint32 p3 = Bbase[(kk+3)*64 + o];
                ull hv = (ull)(p0&0xffffu) | ((ull)(p1&0xffffu)<<16)
                       | ((ull)(p2&0xffffu)<<32) | ((ull)(p3&0xffffu)<<48);
                ull lv = (ull)(p0>>16) | ((ull)(p1>>16)<<16)
                       | ((ull)(p2>>16)<<32) | ((ull)(p3>>16)<<48);
                *(ull*)&Bth[o*SKP + kk] = hv;
                *(ull*)&Btl[o*SKP + kk] = lv;
            }
        }
        __syncthreads();

        #pragma unroll
        for (int ks = 0; ks < 8; ks++) {
            const uint32 kk = ks * 16;
            uint32 ah[2][4], al[2][4];
            #pragma unroll
            for (int mt = 0; mt < 2; mt++) {
                uint32 ab = (uint32)(((m0 + mt*16 + alrow)*SKP + kk + a_koff) << 1);
                LDSM4(ah[mt][0],ah[mt][1],ah[mt][2],ah[mt][3], sAh + ab);
                LDSM4(al[mt][0],al[mt][1],al[mt][2],al[mt][3], sAl + ab);
            }
            #pragma unroll
            for (int g = 0; g < 2; g++) {
                int n0 = cg*32 + g*16;
                uint32 bh[4], bl[4];
                uint32 bb = (uint32)(((n0 + brow)*SKP + kk + b_koff) << 1);
                LDSM4(bh[0],bh[1],bh[2],bh[3], sBh + bb);
                LDSM4(bl[0],bl[1],bl[2],bl[3], sBl + bb);
                #pragma unroll
                for (int mt = 0; mt < 2; mt++)
                    MMA_TERMS(acc[mt*4+g*2], acc[mt*4+g*2+1], ah[mt], al[mt], bh, bl);
            }
        }
    }

    float* P = part + ((long)s*Bq + b)*Nq*Mq;
    const int erow = (lane >> 2), ecol = (lane & 3) << 1;
    #pragma unroll
    for (int mt = 0; mt < 2; mt++) {
        int r0 = m0 + mt*16 + erow;
        #pragma unroll
        for (int g = 0; g < 2; g++)
            #pragma unroll
            for (int hcol = 0; hcol < 2; hcol++) {
                int t = mt*4 + g*2 + hcol;
                int col = cg*32 + g*16 + hcol*8 + ecol;
                *(float2*)&P[r0*64 + col]     = make_float2(acc[t][0], acc[t][1]);
                *(float2*)&P[(r0+8)*64 + col] = make_float2(acc[t][2], acc[t][3]);
            }
    }
}

// ---- ONE merged prep kernel (transposes, packs, init_h) --------------------
#define W3P_N (KO*64)
#define GRU_N (64*192)
#define W1_N  (256*128)
#define W2_N  (128*256)
#define IH_N  (NNODE*64)
#define PREP_TOTAL (W3P_N + GRU_N + W1_N + W2_N + IH_N)

__global__ void prep_all(const float* __restrict__ We3,
                         const float* __restrict__ Wih, const float* __restrict__ Whh,
                         const float* __restrict__ We1, const float* __restrict__ We2,
                         const float* __restrict__ h_in,
                         uint32* __restrict__ w3p,
                         float* __restrict__ WihT, float* __restrict__ WhhT,
                         uint32* __restrict__ w1p, uint32* __restrict__ w2p,
                         float* __restrict__ h, uint32* __restrict__ hp)
{
    int idx = blockIdx.x*256 + threadIdx.x;
    if (idx < W3P_N) {
        int n = idx>>6, i = idx&63;
        w3p[idx] = packsplit(We3[(long)(n>>6)*4096 + (n&63)*64 + i]);
    } else if (idx < W3P_N + GRU_N) {
        int j2 = idx - W3P_N;
        int i = j2/192, j = j2%192;
        WihT[j2] = Wih[j*64+i];
        WhhT[j2] = Whh[j*64+i];
    } else if (idx < W3P_N + GRU_N + W1_N) {
        int i = idx - W3P_N - GRU_N;
        int n = i >> 7, k = i & 127;
        w1p[i] = packsplit(We1[k*256 + n]);
    } else if (idx < W3P_N + GRU_N + W1_N + W2_N) {
        int j = idx - W3P_N - GRU_N - W1_N;
        int n = j >> 8, k = j & 255;
        w2p[j] = packsplit(We2[k*128 + n]);
    } else if (idx < PREP_TOTAL) {
        int j = idx - W3P_N - GRU_N - W1_N - W2_N;
        int node = j>>6, i = j&63;
        float v = (i<INq) ? h_in[node*INq+i] : 0.f;
        h[j] = v;
        hp[j] = packsplit(v);
    }
}

// ============ fp32 FFMA2 SGEMM body (device inline) ========================
template<int ACT, int PACKOUT>
__device__ __forceinline__
void gemm128_body(const float* __restrict__ A, const float* __restrict__ Bm,
                  const float* __restrict__ bias, void* __restrict__ Cv,
                  int Nc, int K, float As[16][132], float Bs[16][128])
{
    const int bm = blockIdx.y*128, bn = blockIdx.x*128;
    const int tid = threadIdx.x;
    const int tr = tid>>4, tc = tid&15;

    ull acc[8][4];
    #pragma unroll
    for (int i=0;i<8;i++)
        #pragma unroll
        for (int j=0;j<4;j++) acc[i][j]=0ull;

    float4 pa[2], pb[2];
    const int ntiles = K>>4;

    #pragma unroll
    for (int i=0;i<2;i++){
        int l = tid + i*256; int q = l&3, r = l>>2;
        pa[i] = *(const float4*)&A[(long)(bm+r)*K + q*4];
    }
    #pragma unroll
    for (int i=0;i<2;i++){
        int l = tid + i*256; int r = l>>5, c = (l&31)*4;
        pb[i] = *(const float4*)&Bm[(long)r*Nc + bn + c];
    }
    #pragma unroll
    for (int i=0;i<2;i++){
        int l = tid + i*256; int q = l&3, r = l>>2;
        As[q*4+0][r]=pa[i].x; As[q*4+1][r]=pa[i].y;
        As[q*4+2][r]=pa[i].z; As[q*4+3][r]=pa[i].w;
    }
    #pragma unroll
    for (int i=0;i<2;i++){
        int l = tid + i*256; int r = l>>5, c = (l&31)*4;
        *(float4*)&Bs[r][c] = pb[i];
    }
    __syncthreads();

    for (int t=0; t<ntiles; t++){
        if (t+1 < ntiles){
            int kt = (t+1)<<4;
            #pragma unroll
            for (int i=0;i<2;i++){
                int l = tid + i*256; int q = l&3, r = l>>2;
                pa[i] = *(const float4*)&A[(long)(bm+r)*K + kt + q*4];
            }
            #pragma unroll
            for (int i=0;i<2;i++){
                int l = tid + i*256; int r = l>>5, c = (l&31)*4;
                pb[i] = *(const float4*)&Bm[(long)(kt+r)*Nc + bn + c];
            }
        }
        #pragma unroll
        for (int k=0;k<16;k++){
            float4 a0 = *(const float4*)&As[k][tr*8];
            float4 a1 = *(const float4*)&As[k][tr*8+4];
            ulonglong2 bb0 = *(const ulonglong2*)&Bs[k][tc*8];
            ulonglong2 bb1 = *(const ulonglong2*)&Bs[k][tc*8+4];
            ull bp0=bb0.x, bp1=bb0.y, bp2=bb1.x, bp3=bb1.y;
            ull a2[8];
            PACK_DUP(a2[0], a0.x); PACK_DUP(a2[1], a0.y);
            PACK_DUP(a2[2], a0.z); PACK_DUP(a2[3], a0.w);
            PACK_DUP(a2[4], a1.x); PACK_DUP(a2[5], a1.y);
            PACK_DUP(a2[6], a1.z); PACK_DUP(a2[7], a1.w);
            #pragma unroll
            for (int i=0;i<8;i++){
                FMA_X2(acc[i][0], a2[i], bp0);
                FMA_X2(acc[i][1], a2[i], bp1);
                FMA_X2(acc[i][2], a2[i], bp2);
                FMA_X2(acc[i][3], a2[i], bp3);
            }
        }
        __syncthreads();
        if (t+1 < ntiles){
            #pragma unroll
            for (int i=0;i<2;i++){
                int l = tid + i*256; int q = l&3, r = l>>2;
                As[q*4+0][r]=pa[i].x; As[q*4+1][r]=pa[i].y;
                As[q*4+2][r]=pa[i].z; As[q*4+3][r]=pa[i].w;
            }
            #pragma unroll
            for (int i=0;i<2;i++){
                int l = tid + i*256; int r = l>>5, c = (l&31)*4;
                *(float4*)&Bs[r][c] = pb[i];
            }
            __syncthreads();
        }
    }

    const int gc0 = bn + tc*8;
    float bv[8];
    #pragma unroll
    for (int j=0;j<8;j++) bv[j] = bias ? bias[gc0+j] : 0.f;
    #pragma unroll
    for (int i=0;i<8;i++){
        int gr = bm + tr*8 + i;
        float o[8];
        #pragma unroll
        for (int j=0;j<4;j++){
            unsigned lo, hi;
            UNPACK2(lo, hi, acc[i][j]);
            o[2*j]   = __uint_as_float(lo) + bv[2*j];
            o[2*j+1] = __uint_as_float(hi) + bv[2*j+1];
        }
        if (ACT==1){
            #pragma unroll
            for (int j=0;j<8;j++) o[j] = fmaxf(o[j], 0.f);
        }
        if (PACKOUT==0){
            float* C = (float*)Cv;
            *(float4*)&C[(long)gr*Nc + gc0]     = make_float4(o[0],o[1],o[2],o[3]);
            *(float4*)&C[(long)gr*Nc + gc0 + 4] = make_float4(o[4],o[5],o[6],o[7]);
        } else {
            uint32* C = (uint32*)Cv;
            uint4 s0 = make_uint4(packsplit(o[0]),packsplit(o[1]),packsplit(o[2]),packsplit(o[3]));
            uint4 s1 = make_uint4(packsplit(o[4]),packsplit(o[5]),packsplit(o[6]),packsplit(o[7]));
            *(uint4*)&C[(long)gr*Nc + gc0]     = s0;
            *(uint4*)&C[(long)gr*Nc + gc0 + 4] = s1;
        }
    }
}

// dual readout GEMM: z selects (gate chain, val chain) operands; relu epilogue
__global__ __launch_bounds__(256)
void gemm128_dualro(const float* __restrict__ A0, const float* __restrict__ B0,
                    const float* __restrict__ bias0, float* __restrict__ C0, int K0,
                    const float* __restrict__ A1, const float* __restrict__ B1,
                    const float* __restrict__ bias1, float* __restrict__ C1, int K1,
                    int Nc)
{
    __shared__ __align__(16) float As[16][132];
    __shared__ __align__(16) float Bs[16][128];
    if (blockIdx.z == 0)
        gemm128_body<1,0>(A0, B0, bias0, C0, Nc, K0, As, Bs);
    else
        gemm128_body<1,0>(A1, B1, bias1, C1, Nc, K1, As, Bs);
}

// ---------------- generic tiled SGEMM body (bounds-checked) ----------------
template<int ACT>
__device__ __forceinline__
void gemm64_body(const float* __restrict__ A, const float* __restrict__ Bm,
                 const float* __restrict__ bias, float* __restrict__ C,
                 int Mr, int Nc, int K,
                 float As[16][65], float Bs[16][64])
{
    const int BM=64, BN=64, BK=16;
    int bm = blockIdx.y*BM, bn = blockIdx.x*BN;
    int tid = threadIdx.x;
    int tr = tid>>4, tc = tid&15;
    float acc[4][4] = {};
    for (int kt=0; kt<K; kt+=BK) {
        #pragma unroll
        for (int i=0;i<4;i++){
            int l = tid + i*256; int r = l>>4, c = l&15;
            int gr = bm+r, gc = kt+c;
            As[c][r] = (gr<Mr && gc<K) ? A[(long)gr*K + gc] : 0.f;
        }
        #pragma unroll
        for (int i=0;i<4;i++){
            int l = tid + i*256; int r = l>>6, c = l&63;
            int gr = kt+r, gc = bn+c;
            Bs[r][c] = (gr<K && gc<Nc) ? Bm[(long)gr*Nc + gc] : 0.f;
        }
        __syncthreads();
        #pragma unroll
        for (int k=0;k<BK;k++){
            float a[4], b[4];
            #pragma unroll
            for (int i=0;i<4;i++) a[i]=As[k][tr*4+i];
            #pragma unroll
            for (int j=0;j<4;j++) b[j]=Bs[k][tc*4+j];
            #pragma unroll
            for (int i=0;i<4;i++)
                #pragma unroll
                for (int j=0;j<4;j++) acc[i][j] = fmaf(a[i],b[j],acc[i][j]);
        }
        __syncthreads();
    }
    #pragma unroll
    for (int i=0;i<4;i++){
        int gr = bm + tr*4 + i;
        if (gr>=Mr) continue;
        #pragma unroll
        for (int j=0;j<4;j++){
            int gc = bn + tc*4 + j;
            if (gc>=Nc) continue;
            float v = acc[i][j] + (bias?bias[gc]:0.f);
            if (ACT==1) v = fmaxf(v,0.f);
            C[(long)gr*Nc + gc] = v;
        }
    }
}

// dual final readout: z0: t1@Wi3->gatel ; z1: v1@Wj3->val  (N=32, K=128)
__global__ void gemm64_dualro(const float* __restrict__ t1, const float* __restrict__ Wi3,
                              const float* __restrict__ bi3, float* __restrict__ gatel,
                              const float* __restrict__ v1, const float* __restrict__ Wj3,
                              const float* __restrict__ bj3, float* __restrict__ val)
{
    __shared__ float As[16][65];
    __shared__ float Bs[16][64];
    if (blockIdx.z == 0)
        gemm64_body<0>(t1, Wi3, bi3, gatel, NNODE, 32, 128, As, Bs);
    else
        gemm64_body<0>(v1, Wj3, bj3, val, NNODE, 32, 128, As, Bs);
}

// dual GRU-gate GEMM: z=0 -> gi = msg@WihT + bih ; z=1 -> gh = h@WhhT + bhh
__global__ void gemm64_dual(const float* __restrict__ msg, const float* __restrict__ h,
                            const float* __restrict__ WihT, const float* __restrict__ WhhT,
                            const float* __restrict__ bih, const float* __restrict__ bhh,
                            float* __restrict__ gi, float* __restrict__ gh)
{
    const int BM=64, BN=64, BK=16;
    const int Nc = 192, K = 64;
    const float* A    = blockIdx.z ? h    : msg;
    const float* Bm   = blockIdx.z ? WhhT : WihT;
    const float* bias = blockIdx.z ? bhh  : bih;
    float* C          = blockIdx.z ? gh   : gi;

    __shared__ float As[BK][BM+1];
    __shared__ float Bs[BK][BN];
    int bm = blockIdx.y*BM, bn = blockIdx.x*BN;
    int tid = threadIdx.x;
    int tr = tid>>4, tc = tid&15;
    float acc[4][4] = {};
    for (int kt=0; kt<K; kt+=BK) {
        #pragma unroll
        for (int i=0;i<4;i++){
            int l = tid + i*256; int r = l>>4, c = l&15;
            As[c][r] = A[(long)(bm+r)*K + kt + c];
        }
        #pragma unroll
        for (int i=0;i<4;i++){
            int l = tid + i*256; int r = l>>6, c = l&63;
            int gc = bn+c;
            Bs[r][c] = (gc<Nc) ? Bm[(long)(kt+r)*Nc + gc] : 0.f;
        }
        __syncthreads();
        #pragma unroll
        for (int k=0;k<BK;k++){
            float a[4], b[4];
            #pragma unroll
            for (int i=0;i<4;i++) a[i]=As[k][tr*4+i];
            #pragma unroll
            for (int j=0;j<4;j++) b[j]=Bs[k][tc*4+j];
            #pragma unroll
            for (int i=0;i<4;i++)
                #pragma unroll
                for (int j=0;j<4;j++) acc[i][j] = fmaf(a[i],b[j],acc[i][j]);
        }
        __syncthreads();
    }
    #pragma unroll
    for (int i=0;i<4;i++){
        int gr = bm + tr*4 + i;
        #pragma unroll
        for (int j=0;j<4;j++){
            int gc = bn + tc*4 + j;
            if (gc>=Nc) continue;
            C[(long)gr*Nc + gc] = acc[i][j] + bias[gc];
        }
    }
}

__global__ void msg_reduce(const float* __restrict__ part, const float* __restrict__ bmsg,
                           float* __restrict__ msg)
{
    int idx = blockIdx.x*256 + threadIdx.x;
    if (idx >= NNODE*Mq) return;
    int node = idx>>6, o = idx&63;
    int b = node>>7, v = node&127;
    float s = bmsg[b*64+o];
    #pragma unroll 8
    for (int sp=0; sp<SPLITS; sp++)
        s += part[((long)sp*Bq + b)*Nq*Mq + v*64 + o];
    msg[idx]=s;
}

__global__ void bias_msg_kernel(const float* __restrict__ h, const float* __restrict__ be3,
                                float* __restrict__ bmsg)
{
    int b = blockIdx.x;
    __shared__ float hs[64];
    int t = threadIdx.x;
    float s = 0.f;
    for (int w=0; w<Nq; w++) s += h[((long)b*Nq+w)*64 + t];
    hs[t] = s;
    __syncthreads();
    float r = 0.f;
    for (int i=0;i<64;i++) r = fmaf(be3[t*64+i], hs[i], r);
    bmsg[b*64+t] = r;
}

__global__ void gru_update(const float* __restrict__ gi, const float* __restrict__ gh,
                           const int* __restrict__ g_size, float* __restrict__ h,
                           uint32* __restrict__ hp){
    int idx = blockIdx.x*256+threadIdx.x;
    if (idx>=NNODE*64) return;
    int node = idx>>6, i = idx&63;
    int b = node>>7, v = node&127;
    float r = 1.f/(1.f+expf(-(gi[node*192+i]     + gh[node*192+i])));
    float z = 1.f/(1.f+expf(-(gi[node*192+64+i]  + gh[node*192+64+i])));
    float n = tanhf(gi[node*192+128+i] + r*gh[node*192+128+i]);
    float hv = (1.f-z)*n + z*h[idx];
    hv = (v < g_size[b]) ? hv : 0.f;
    h[idx] = hv;
    hp[idx] = packsplit(hv);
}

__global__ void concat_kernel(const float* __restrict__ h, const float* __restrict__ h_in,
                              float* __restrict__ cat){
    int idx = blockIdx.x*256+threadIdx.x;
    if (idx>=NNODE*96) return;
    int node=idx/96, c=idx%96;
    cat[idx] = (c<64)? h[node*64+c] : h_in[node*INq + (c-64)];
}

__global__ void res_reduce(const float* __restrict__ gatel, const float* __restrict__ val,
                           const int* __restrict__ g_size, float* __restrict__ res){
    int t = blockIdx.x, b = blockIdx.y;
    int tid = threadIdx.x;
    int gs = g_size[b];
    float s = 0.f;
    if (tid < gs) {
        int node = b*Nq+tid;
        float gl = gatel[node*Tq+t];
        s = (1.f/(1.f+expf(-gl))) * val[node*Tq+t];
    }
    __shared__ float sm[128];
    sm[tid]=s; __syncthreads();
    for (int st=64; st>0; st>>=1){ if(tid<st) sm[tid]+=sm[tid+st]; __syncthreads(); }
    if (tid==0) res[b*Tq+t]=sm[0];
}

__global__ void logsoftmax_kernel(const float* __restrict__ res, float* __restrict__ out){
    int b = blockIdx.x; int t = threadIdx.x;
    float x = res[b*Tq+t];
    float m = x;
    for (int o=16;o>0;o>>=1) m = fmaxf(m, __shfl_xor_sync(0xffffffffu, m, o));
    float e = expf(x-m), s=e;
    for (int o=16;o>0;o>>=1) s += __shfl_xor_sync(0xffffffffu, s, o);
    out[b*Tq+t] = x - m - logf(s);
}

// ---------------------------------------------------------------------------
static inline void* symp(const void* symbol){
    void* p = nullptr;
    cudaGetSymbolAddress(&p, symbol);
    return p;
}

extern "C" void kernel_launch(void* const* d_in, const int* in_sizes, int n_in,
                              void* d_out, int out_size)
{
    const float* h_in = (const float*)d_in[0];
    const float* am   = (const float*)d_in[1];
    const int*   gsz  = (const int*)d_in[2];
    const float* We0=(const float*)d_in[3];  const float* be0=(const float*)d_in[4];
    const float* We1=(const float*)d_in[5];  const float* be1=(const float*)d_in[6];
    const float* We2=(const float*)d_in[7];  const float* be2=(const float*)d_in[8];
    const float* We3=(const float*)d_in[9];  const float* be3=(const float*)d_in[10];
    const float* Wih=(const float*)d_in[11]; const float* Whh=(const float*)d_in[12];
    const float* bih=(const float*)d_in[13]; const float* bhh=(const float*)d_in[14];
    const float* Wi0=(const float*)d_in[15]; const float* bi0=(const float*)d_in[16];
    const float* Wj0=(const float*)d_in[17]; const float* bj0=(const float*)d_in[18];
    const float* Wi1=(const float*)d_in[19]; const float* bi1=(const float*)d_in[20];
    const float* Wj1=(const float*)d_in[21]; const float* bj1=(const float*)d_in[22];
    const float* Wi2=(const float*)d_in[23]; const float* bi2=(const float*)d_in[24];
    const float* Wj2=(const float*)d_in[25]; const float* bj2=(const float*)d_in[26];
    const float* Wi3=(const float*)d_in[27]; const float* bi3=(const float*)d_in[28];
    const float* Wj3=(const float*)d_in[29]; const float* bj3=(const float*)d_in[30];
    (void)in_sizes; (void)n_in; (void)out_size;

    uint32* e256p= (uint32*)symp(d_e256p);
    uint32* fp   = (uint32*)symp(d_fp);
    uint32* w1p  = (uint32*)symp(d_w1p);
    uint32* w2p  = (uint32*)symp(d_w2p);
    uint32* w3p  = (uint32*)symp(d_w3p);
    uint32* g    = (uint32*)symp(d_g);
    float* h    = (float*)symp(d_h);
    uint32* hp   = (uint32*)symp(d_hp);
    float* part = (float*)symp(d_part);  float* msg  = (float*)symp(d_msg);
    float* gi   = (float*)symp(d_gi);    float* gh   = (float*)symp(d_gh);
    float* WihT = (float*)symp(d_WihT);
    float* WhhT = (float*)symp(d_WhhT);  float* bmsg = (float*)symp(d_bmsg);
    float* cat  = (float*)symp(d_cat);   float* t1   = (float*)symp(d_t1);
    float* t2   = (float*)symp(d_t2);    float* v1   = (float*)symp(d_v1);
    float* v2   = (float*)symp(d_v2);    float* gatel= (float*)symp(d_gatel);
    float* val  = (float*)symp(d_val);   float* res  = (float*)symp(d_res);
    float* out  = (float*)d_out;

    // one-time host-side resources (created on first, uncaptured, call)
    static cudaStream_t s2 = nullptr;
    static cudaEvent_t evFork = nullptr, evJoin = nullptr;
    if (!s2) {
        cudaStreamCreateWithFlags(&s2, cudaStreamNonBlocking);
        cudaEventCreateWithFlags(&evFork, cudaEventDisableTiming);
        cudaEventCreateWithFlags(&evJoin, cudaEventDisableTiming);
        cudaFuncSetAttribute(mlp1_mma64,
                             cudaFuncAttributeMaxDynamicSharedMemorySize, M64_SMEM);
        cudaFuncSetAttribute(mlp2_mma64,
                             cudaFuncAttributeMaxDynamicSharedMemorySize, M64_SMEM);
        cudaFuncSetAttribute(splitk_mma,
                             cudaFuncAttributeMaxDynamicSharedMemorySize, SPLITK_SMEM);
        cudaFuncSetAttribute(gmma,
                             cudaFuncAttributeMaxDynamicSharedMemorySize, GMMA_SMEM);
    }

    // merged prep (weight packs/transposes + init_h/hp, 1 launch)
    prep_all<<<(PREP_TOTAL+255)/256,256>>>(We3, Wih, Whh, We1, We2, h_in,
                                           w3p, WihT, WhhT, w1p, w2p, h, hp);

    // fork: layer-0 message prep (needs only prep_all) overlaps the edge MLP
    cudaEventRecord(evFork, 0);
    cudaStreamWaitEvent(s2, evFork, 0);
    gmma<<<dim3(64,32),256,GMMA_SMEM,s2>>>(hp, w3p, g);
    bias_msg_kernel<<<Bq,64,0,s2>>>(h, be3, bmsg);
    cudaEventRecord(evJoin, s2);

    // edge MLP: 4 -> 128 -> 256 -> 128 (relu each), on main stream
    mlp1_mma64<<<NE/64,256,M64_SMEM>>>(am, We0, be0, w1p, be1, e256p);
    mlp2_mma64<<<NE/64,256,M64_SMEM>>>(e256p, w2p, be2, fp);

    cudaStreamWaitEvent(0, evJoin, 0);

    for (int layer=0; layer<3; layer++) {
        if (layer > 0) {
            gmma<<<dim3(64,32),256,GMMA_SMEM>>>(hp, w3p, g);
            bias_msg_kernel<<<Bq,64>>>(h, be3, bmsg);
        }
        splitk_mma<<<dim3(SPLITS,Bq), 256, SPLITK_SMEM>>>(fp, g, part);
        msg_reduce<<<512,256>>>(part, bmsg, msg);
        gemm64_dual<<<dim3(3,32,2), 256>>>(msg, h, WihT, WhhT, bih, bhh, gi, gh);
        gru_update<<<512,256>>>(gi, gh, gsz, h, hp);
    }

    // readout: gate & val chains fused per layer via blockIdx.z
    concat_kernel<<<768,256>>>(h, h_in, cat);
    gemm128_dualro<<<dim3(1,16,2), 256>>>(cat, Wi0, bi0, t1, 96,
                                          h,   Wj0, bj0, v1, 64, 128);
    gemm128_dualro<<<dim3(2,16,2), 256>>>(t1, Wi1, bi1, t2, 128,
                                          v1, Wj1, bj1, v2, 128, 256);
    gemm128_dualro<<<dim3(1,16,2), 256>>>(t2, Wi2, bi2, t1, 256,
                                          v2, Wj2, bj2, v1, 256, 128);
    gemm64_dualro<<<dim3(1,32,2), 256>>>(t1, Wi3, bi3, gatel,
                                         v1, Wj3, bj3, val);

    res_reduce<<<dim3(Tq,Bq),128>>>(gatel, val, gsz, res);
    logsoftmax_kernel<<<Bq,Tq>>>(res, out);
}

// round 17
// speedup vs baseline: 1.4941x; 1.0112x over previous
#include <cuda_runtime.h>
#include <cuda_bf16.h>
#include <math.h>
#include <stdint.h>

#define Bq 16
#define Nq 128
#define Hq 64
#define Mq 64
#define INq 32
#define Tq 32
#define NE (Bq*Nq*Nq)        /* 262144 edges */
#define NNODE (Bq*Nq)        /* 2048 nodes  */
#define KO 8192              /* 128*64      */
#define KBIG (Nq*128)        /* 16384       */
#define SPLITS 32
#define KS (KBIG/SPLITS)     /* 512         */

typedef unsigned long long ull;
typedef unsigned int uint32;

// ---- packed f32x2 helpers (sm_103a) ---------------------------------------
#define PACK_DUP(d, s) asm("mov.b64 %0, {%1, %1};" : "=l"(d) : "r"(__float_as_uint(s)))
#define FMA_X2(d, a, b) asm("fma.rn.f32x2 %0, %1, %2, %0;" : "+l"(d) : "l"(a), "l"(b))
#define UNPACK2(lo, hi, s) asm("mov.b64 {%0, %1}, %2;" : "=r"(lo), "=r"(hi) : "l"(s))

// ---- mma.sync / ldmatrix helpers ------------------------------------------
__device__ __forceinline__ uint32 smem_u32(const void* p) {
    uint32 a;
    asm("{ .reg .u64 t; cvta.to.shared.u64 t, %1; cvt.u32.u64 %0, t; }" : "=r"(a) : "l"(p));
    return a;
}

#define LDSM4(r0,r1,r2,r3,addr) \
    asm volatile("ldmatrix.sync.aligned.m8n8.x4.shared.b16 {%0,%1,%2,%3}, [%4];" \
        : "=r"(r0),"=r"(r1),"=r"(r2),"=r"(r3) : "r"(addr))

__device__ __forceinline__ void mma_bf16(float* c, const uint32* a, uint32 b0, uint32 b1){
    asm volatile("mma.sync.aligned.m16n8k16.row.col.f32.bf16.bf16.f32 "
        "{%0,%1,%2,%3},{%4,%5,%6,%7},{%8,%9},{%0,%1,%2,%3};"
        : "+f"(c[0]),"+f"(c[1]),"+f"(c[2]),"+f"(c[3])
        : "r"(a[0]),"r"(a[1]),"r"(a[2]),"r"(a[3]),"r"(b0),"r"(b1));
}

__device__ __forceinline__ uint32 packsplit(float v){
    __nv_bfloat16 h = __float2bfloat16(v);
    float r = v - __bfloat162float(h);
    __nv_bfloat16 l = __float2bfloat16(r);
    return (uint32)__bfloat16_as_ushort(h) | ((uint32)__bfloat16_as_ushort(l) << 16);
}

#define SPLIT8(e0,e1,e2,e3,e4,e5,e6,e7,H,L) do { \
    H.x=(e0&0xffffu)|(e1<<16); H.y=(e2&0xffffu)|(e3<<16); \
    H.z=(e4&0xffffu)|(e5<<16); H.w=(e6&0xffffu)|(e7<<16); \
    L.x=(e0>>16)|(e1&0xffff0000u); L.y=(e2>>16)|(e3&0xffff0000u); \
    L.z=(e4>>16)|(e5&0xffff0000u); L.w=(e6>>16)|(e7&0xffff0000u); \
} while(0)

#define MMA_TERMS(c0, c1, ah, al, bh, bl) do { \
    mma_bf16(c0, ah, bh[0], bh[1]); \
    mma_bf16(c0, ah, bl[0], bl[1]); \
    mma_bf16(c0, al, bh[0], bh[1]); \
    mma_bf16(c1, ah, bh[2], bh[3]); \
    mma_bf16(c1, ah, bl[2], bl[3]); \
    mma_bf16(c1, al, bh[2], bh[3]); \
} while(0)

// ---------------- scratch (static device globals; no allocation) ----------
__device__ uint32 d_e256p[(long)NE*256]; // mlp1 out, packed bf16 hi/lo
__device__ uint32 d_fp[(long)NE*128];    // edge features, packed bf16 hi/lo
__device__ uint32 d_w1p[256*128];        // W1^T packed [NOUT=256][K=128]
__device__ uint32 d_w2p[128*256];        // W2^T packed [NOUT=128][K=256]
__device__ uint32 d_w3p[KO*64];          // W3t packed [n=8192][k=64]
__device__ float d_h[NNODE*Hq];
__device__ uint32 d_hp[NNODE*Hq];        // h packed bf16 hi/lo
__device__ uint32 d_g[(long)NNODE*KO];   // g packed bf16 hi/lo
__device__ float d_part[(long)SPLITS*Bq*Nq*Mq];
__device__ float d_msg[NNODE*Mq];
__device__ float d_gi[NNODE*192];
__device__ float d_gh[NNODE*192];
__device__ float d_WihT[Hq*192];
__device__ float d_WhhT[Hq*192];
__device__ float d_bmsg[Bq*Mq];
__device__ float d_cat[NNODE*96];
__device__ float d_t1[NNODE*256];
__device__ float d_t2[NNODE*256];
__device__ float d_v1[NNODE*256];
__device__ float d_v2[NNODE*256];
__device__ float d_gatel[NNODE*Tq];
__device__ float d_val[NNODE*Tq];
__device__ float d_res[Bq*Tq];

// ==== 64-row MLP layer kernels (R8 config: 256 thr, 8 warps, 32x32 tiles) ==
#define KP64 136
#define M64_SMEM ((2*64*KP64 + 2*128*KP64)*2)   /* 104448 */

__global__ __launch_bounds__(256)
void mlp1_mma64(const float* __restrict__ am,
                const float* __restrict__ We0, const float* __restrict__ be0,
                const uint32* __restrict__ Wp, const float* __restrict__ bias,
                uint32* __restrict__ Cout)
{
    extern __shared__ __align__(16) char smem[];
    __nv_bfloat16* Ah = (__nv_bfloat16*)smem;          // [64][KP64]
    __nv_bfloat16* Al = Ah + 64*KP64;
    __nv_bfloat16* Wh = Al + 64*KP64;                  // [128][KP64]
    __nv_bfloat16* Wl = Wh + 128*KP64;

    const int tid = threadIdx.x;
    const int wid = tid >> 5, lane = tid & 31;
    const long bm = (long)blockIdx.x * 64;
    const int m0 = (wid & 1) * 32;
    const int cg = wid >> 1;                           // 4 col groups of 32

    const uint32 sAh = smem_u32(Ah), sAl = smem_u32(Al);
    const uint32 sWh = smem_u32(Wh), sWl = smem_u32(Wl);

    {
        int r = tid >> 2, seg = tid & 3;
        float4 a = *(const float4*)&am[(bm + r) * 4];
        #pragma unroll
        for (int c4 = 0; c4 < 8; c4++) {
            int c = seg*32 + c4*4;
            ull hv = 0, lv = 0;
            #pragma unroll
            for (int j = 0; j < 4; j++) {
                int n = c + j;
                float v = be0[n];
                v = fmaf(a.x, We0[n], v);
                v = fmaf(a.y, We0[128+n], v);
                v = fmaf(a.z, We0[256+n], v);
                v = fmaf(a.w, We0[384+n], v);
                v = fmaxf(v, 0.f);
                uint32 p = packsplit(v);
                hv |= ((ull)(p & 0xffffu)) << (16*j);
                lv |= ((ull)(p >> 16)) << (16*j);
            }
            *(ull*)&Ah[r*KP64 + c] = hv;
            *(ull*)&Al[r*KP64 + c] = lv;
        }
    }

    const int alrow = lane & 15;
    const uint32 a_koff = ((lane >> 4) << 3);
    const int brow = ((lane >> 4) & 1) * 8 + (lane & 7);
    const uint32 b_koff = ((lane >> 3) & 1) * 8;
    const int erow = (lane >> 2);
    const int ecol = (lane & 3) << 1;

    #pragma unroll 1
    for (int nh = 0; nh < 2; nh++) {
        __syncthreads();
        for (int gi = tid; gi < 128*16; gi += 256) {
            int n = gi >> 4, k = (gi & 15) * 8;
            const uint32* src = &Wp[(long)(nh*128 + n)*128 + k];
            uint4 v0 = *(const uint4*)src, v1 = *(const uint4*)(src+4);
            uint4 H, L;
            SPLIT8(v0.x,v0.y,v0.z,v0.w,v1.x,v1.y,v1.z,v1.w,H,L);
            *(uint4*)&Wh[n*KP64 + k] = H;
            *(uint4*)&Wl[n*KP64 + k] = L;
        }
        __syncthreads();

        float acc[8][4] = {};
        #pragma unroll
        for (int ks = 0; ks < 8; ks++) {
            const uint32 kk = ks * 16;
            uint32 ah[2][4], al[2][4];
            #pragma unroll
            for (int mt = 0; mt < 2; mt++) {
                uint32 ab = (uint32)(((m0 + mt*16 + alrow)*KP64 + kk + a_koff) << 1);
                LDSM4(ah[mt][0],ah[mt][1],ah[mt][2],ah[mt][3], sAh + ab);
                LDSM4(al[mt][0],al[mt][1],al[mt][2],al[mt][3], sAl + ab);
            }
            #pragma unroll
            for (int g = 0; g < 2; g++) {
                int n0 = cg*32 + g*16;
                uint32 bh[4], bl[4];
                uint32 bb = (uint32)(((n0 + brow)*KP64 + kk + b_koff) << 1);
                LDSM4(bh[0],bh[1],bh[2],bh[3], sWh + bb);
                LDSM4(bl[0],bl[1],bl[2],bl[3], sWl + bb);
                #pragma unroll
                for (int mt = 0; mt < 2; mt++)
                    MMA_TERMS(acc[mt*4+g*2], acc[mt*4+g*2+1], ah[mt], al[mt], bh, bl);
            }
        }
        #pragma unroll
        for (int mt = 0; mt < 2; mt++) {
            long r0 = bm + m0 + mt*16 + erow;
            #pragma unroll
            for (int g = 0; g < 2; g++)
                #pragma unroll
                for (int hcol = 0; hcol < 2; hcol++) {
                    int t = mt*4 + g*2 + hcol;
                    int col = nh*128 + cg*32 + g*16 + hcol*8 + ecol;
                    float b0 = bias[col], b1 = bias[col+1];
                    float v0 = fmaxf(acc[t][0]+b0, 0.f), v1 = fmaxf(acc[t][1]+b1, 0.f);
                    float v2 = fmaxf(acc[t][2]+b0, 0.f), v3 = fmaxf(acc[t][3]+b1, 0.f);
                    *(uint2*)&Cout[r0*256 + col]     = make_uint2(packsplit(v0), packsplit(v1));
                    *(uint2*)&Cout[(r0+8)*256 + col] = make_uint2(packsplit(v2), packsplit(v3));
                }
        }
    }
}

__global__ __launch_bounds__(256)
void mlp2_mma64(const uint32* __restrict__ Ap, const uint32* __restrict__ Wp,
                const float* __restrict__ bias, uint32* __restrict__ Cout)
{
    extern __shared__ __align__(16) char smem[];
    __nv_bfloat16* Ah = (__nv_bfloat16*)smem;          // [64][KP64]
    __nv_bfloat16* Al = Ah + 64*KP64;
    __nv_bfloat16* Wh = Al + 64*KP64;                  // [128][KP64]
    __nv_bfloat16* Wl = Wh + 128*KP64;

    const int tid = threadIdx.x;
    const int wid = tid >> 5, lane = tid & 31;
    const long bm = (long)blockIdx.x * 64;
    const int m0 = (wid & 1) * 32;
    const int cg = wid >> 1;

    const uint32 sAh = smem_u32(Ah), sAl = smem_u32(Al);
    const uint32 sWh = smem_u32(Wh), sWl = smem_u32(Wl);

    const int alrow = lane & 15;
    const uint32 a_koff = ((lane >> 4) << 3);
    const int brow = ((lane >> 4) & 1) * 8 + (lane & 7);
    const uint32 b_koff = ((lane >> 3) & 1) * 8;

    float acc[8][4] = {};

    #pragma unroll 1
    for (int ck = 0; ck < 2; ck++) {
        __syncthreads();
        for (int gi = tid; gi < 64*16; gi += 256) {
            int r = gi >> 4, k = (gi & 15) * 8;
            const uint32* src = &Ap[(bm + r)*256 + ck*128 + k];
            uint4 v0 = *(const uint4*)src, v1 = *(const uint4*)(src+4);
            uint4 H, L;
            SPLIT8(v0.x,v0.y,v0.z,v0.w,v1.x,v1.y,v1.z,v1.w,H,L);
            *(uint4*)&Ah[r*KP64 + k] = H;
            *(uint4*)&Al[r*KP64 + k] = L;
        }
        for (int gi = tid; gi < 128*16; gi += 256) {
            int n = gi >> 4, k = (gi & 15) * 8;
            const uint32* src = &Wp[(long)n*256 + ck*128 + k];
            uint4 v0 = *(const uint4*)src, v1 = *(const uint4*)(src+4);
            uint4 H, L;
            SPLIT8(v0.x,v0.y,v0.z,v0.w,v1.x,v1.y,v1.z,v1.w,H,L);
            *(uint4*)&Wh[n*KP64 + k] = H;
            *(uint4*)&Wl[n*KP64 + k] = L;
        }
        __syncthreads();

        #pragma unroll
        for (int ks = 0; ks < 8; ks++) {
            const uint32 kk = ks * 16;
            uint32 ah[2][4], al[2][4];
            #pragma unroll
            for (int mt = 0; mt < 2; mt++) {
                uint32 ab = (uint32)(((m0 + mt*16 + alrow)*KP64 + kk + a_koff) << 1);
                LDSM4(ah[mt][0],ah[mt][1],ah[mt][2],ah[mt][3], sAh + ab);
                LDSM4(al[mt][0],al[mt][1],al[mt][2],al[mt][3], sAl + ab);
            }
            #pragma unroll
            for (int g = 0; g < 2; g++) {
                int n0 = cg*32 + g*16;
                uint32 bh[4], bl[4];
                uint32 bb = (uint32)(((n0 + brow)*KP64 + kk + b_koff) << 1);
                LDSM4(bh[0],bh[1],bh[2],bh[3], sWh + bb);
                LDSM4(bl[0],bl[1],bl[2],bl[3], sWl + bb);
                #pragma unroll
                for (int mt = 0; mt < 2; mt++)
                    MMA_TERMS(acc[mt*4+g*2], acc[mt*4+g*2+1], ah[mt], al[mt], bh, bl);
            }
        }
    }

    const int erow = (lane >> 2), ecol = (lane & 3) << 1;
    #pragma unroll
    for (int mt = 0; mt < 2; mt++) {
        long r0 = bm + m0 + mt*16 + erow;
        #pragma unroll
        for (int g = 0; g < 2; g++)
            #pragma unroll
            for (int hcol = 0; hcol < 2; hcol++) {
                int t = mt*4 + g*2 + hcol;
                int col = cg*32 + g*16 + hcol*8 + ecol;
                float b0 = bias[col], b1 = bias[col+1];
                float v0 = fmaxf(acc[t][0]+b0, 0.f), v1 = fmaxf(acc[t][1]+b1, 0.f);
                float v2 = fmaxf(acc[t][2]+b0, 0.f), v3 = fmaxf(acc[t][3]+b1, 0.f);
                *(uint2*)&Cout[r0*128 + col]     = make_uint2(packsplit(v0), packsplit(v1));
                *(uint2*)&Cout[(r0+8)*128 + col] = make_uint2(packsplit(v2), packsplit(v3));
            }
    }
}

// ====== g-GEMM on tensor path: g[2048,8192] = hp[2048,64] @ w3p^T ==========
#define KPG 72
#define GMMA_SMEM ((2*64*KPG + 2*128*KPG)*2)   /* 55296 */

__global__ __launch_bounds__(256,3)
void gmma(const uint32* __restrict__ hp, const uint32* __restrict__ w3p,
          uint32* __restrict__ g)
{
    extern __shared__ __align__(16) char smem[];
    __nv_bfloat16* Ah = (__nv_bfloat16*)smem;          // [64][KPG]
    __nv_bfloat16* Al = Ah + 64*KPG;
    __nv_bfloat16* Wh = Al + 64*KPG;                   // [128][KPG]
    __nv_bfloat16* Wl = Wh + 128*KPG;

    const int tid = threadIdx.x;
    const int wid = tid >> 5, lane = tid & 31;
    const long bm = (long)blockIdx.y * 64;
    const int bn = blockIdx.x * 128;
    const int m0 = (wid & 1) * 32;
    const int cg = wid >> 1;

    const uint32 sAh = smem_u32(Ah), sAl = smem_u32(Al);
    const uint32 sWh = smem_u32(Wh), sWl = smem_u32(Wl);

    for (int gi = tid; gi < 64*8; gi += 256) {
        int r = gi >> 3, k = (gi & 7) * 8;
        const uint32* src = &hp[(bm + r)*64 + k];
        uint4 v0 = *(const uint4*)src, v1 = *(const uint4*)(src+4);
        uint4 H, L;
        SPLIT8(v0.x,v0.y,v0.z,v0.w,v1.x,v1.y,v1.z,v1.w,H,L);
        *(uint4*)&Ah[r*KPG + k] = H;
        *(uint4*)&Al[r*KPG + k] = L;
    }
    for (int gi = tid; gi < 128*8; gi += 256) {
        int n = gi >> 3, k = (gi & 7) * 8;
        const uint32* src = &w3p[(long)(bn + n)*64 + k];
        uint4 v0 = *(const uint4*)src, v1 = *(const uint4*)(src+4);
        uint4 H, L;
        SPLIT8(v0.x,v0.y,v0.z,v0.w,v1.x,v1.y,v1.z,v1.w,H,L);
        *(uint4*)&Wh[n*KPG + k] = H;
        *(uint4*)&Wl[n*KPG + k] = L;
    }
    __syncthreads();

    const int alrow = lane & 15;
    const uint32 a_koff = ((lane >> 4) << 3);
    const int brow = ((lane >> 4) & 1) * 8 + (lane & 7);
    const uint32 b_koff = ((lane >> 3) & 1) * 8;

    float acc[8][4] = {};
    #pragma unroll
    for (int ks = 0; ks < 4; ks++) {
        const uint32 kk = ks * 16;
        uint32 ah[2][4], al[2][4];
        #pragma unroll
        for (int mt = 0; mt < 2; mt++) {
            uint32 ab = (uint32)(((m0 + mt*16 + alrow)*KPG + kk + a_koff) << 1);
            LDSM4(ah[mt][0],ah[mt][1],ah[mt][2],ah[mt][3], sAh + ab);
            LDSM4(al[mt][0],al[mt][1],al[mt][2],al[mt][3], sAl + ab);
        }
        #pragma unroll
        for (int gg = 0; gg < 2; gg++) {
            int n0 = cg*32 + gg*16;
            uint32 bh[4], bl[4];
            uint32 bb = (uint32)(((n0 + brow)*KPG + kk + b_koff) << 1);
            LDSM4(bh[0],bh[1],bh[2],bh[3], sWh + bb);
            LDSM4(bl[0],bl[1],bl[2],bl[3], sWl + bb);
            #pragma unroll
            for (int mt = 0; mt < 2; mt++)
                MMA_TERMS(acc[mt*4+gg*2], acc[mt*4+gg*2+1], ah[mt], al[mt], bh, bl);
        }
    }

    const int erow = (lane >> 2), ecol = (lane & 3) << 1;
    #pragma unroll
    for (int mt = 0; mt < 2; mt++) {
        long r0 = bm + m0 + mt*16 + erow;
        #pragma unroll
        for (int gg = 0; gg < 2; gg++)
            #pragma unroll
            for (int hcol = 0; hcol < 2; hcol++) {
                int t = mt*4 + gg*2 + hcol;
                int col = bn + cg*32 + gg*16 + hcol*8 + ecol;
                *(uint2*)&g[r0*KO + col]      = make_uint2(packsplit(acc[t][0]), packsplit(acc[t][1]));
                *(uint2*)&g[(r0+8)*KO + col]  = make_uint2(packsplit(acc[t][2]), packsplit(acc[t][3]));
            }
    }
}

// ============== split-K msg contraction via mma (bf16 3-term) ==============
#define SKP 136
#define SPLITK_SMEM ((2*128*SKP + 2*64*SKP)*2)  /* 104448 */

__global__ __launch_bounds__(256)
void splitk_mma(const uint32* __restrict__ fp, const uint32* __restrict__ gp,
                float* __restrict__ part)
{
    extern __shared__ __align__(16) char smem[];
    __nv_bfloat16* Ah  = (__nv_bfloat16*)smem;          // [128][SKP]
    __nv_bfloat16* Al  = Ah + 128*SKP;
    __nv_bfloat16* Bth = Al + 128*SKP;                  // [64][SKP]
    __nv_bfloat16* Btl = Bth + 64*SKP;

    const int s = blockIdx.x, b = blockIdx.y;
    const int tid = threadIdx.x;
    const int wid = tid >> 5, lane = tid & 31;
    const int m0 = (wid & 3) * 32;
    const int cg = wid >> 2;

    const uint32 sAh = smem_u32(Ah),  sAl = smem_u32(Al);
    const uint32 sBh = smem_u32(Bth), sBl = smem_u32(Btl);

    const int alrow = lane & 15;
    const uint32 a_koff = ((lane >> 4) << 3);
    const int brow = ((lane >> 4) & 1) * 8 + (lane & 7);
    const uint32 b_koff = ((lane >> 3) & 1) * 8;

    float acc[8][4] = {};

    #pragma unroll 1
    for (int ck = 0; ck < KS/128; ck++) {
        const int k0 = s*KS + ck*128;
        if (ck > 0) __syncthreads();

        const uint32* Abase = fp + (long)b*Nq*KBIG + k0;
        for (int gi = tid; gi < 128*16; gi += 256) {
            int r = gi >> 4, k = (gi & 15) * 8;
            const uint32* src = Abase + (long)r*KBIG + k;
            uint4 v0 = *(const uint4*)src, v1 = *(const uint4*)(src+4);
            uint4 H, L;
            SPLIT8(v0.x,v0.y,v0.z,v0.w,v1.x,v1.y,v1.z,v1.w,H,L);
            *(uint4*)&Ah[r*SKP + k] = H;
            *(uint4*)&Al[r*SKP + k] = L;
        }
        const uint32* Bbase = gp + ((long)b*KBIG + k0) * 64;
        {
            int o = tid & 63, kq = (tid >> 6) * 4;
            #pragma unroll
            for (int it = 0; it < 8; it++) {
                int kk = it*16 + kq;
                uint32 p0 = Bbase[(kk+0)*64 + o];
                uint32 p1 = Bbase[(kk+1)*64 + o];
                uint32 p2 = Bbase[(kk+2)*64 + o];
                uint32 p3 = Bbase[(kk+3)*64 + o];
                ull hv = (ull)(p0&0xffffu) | ((ull)(p1&0xffffu)<<16)
                       | ((ull)(p2&0xffffu)<<32) | ((ull)(p3&0xffffu)<<48);
                ull lv = (ull)(p0>>16) | ((ull)(p1>>16)<<16)
                       | ((ull)(p2>>16)<<32) | ((ull)(p3>>16)<<48);
                *(ull*)&Bth[o*SKP + kk] = hv;
                *(ull*)&Btl[o*SKP + kk] = lv;
            }
        }
        __syncthreads();

        #pragma unroll
        for (int ks = 0; ks < 8; ks++) {
            const uint32 kk = ks * 16;
            uint32 ah[2][4], al[2][4];
            #pragma unroll
            for (int mt = 0; mt < 2; mt++) {
                uint32 ab = (uint32)(((m0 + mt*16 + alrow)*SKP + kk + a_koff) << 1);
                LDSM4(ah[mt][0],ah[mt][1],ah[mt][2],ah[mt][3], sAh + ab);
                LDSM4(al[mt][0],al[mt][1],al[mt][2],al[mt][3], sAl + ab);
            }
            #pragma unroll
            for (int g = 0; g < 2; g++) {
                int n0 = cg*32 + g*16;
                uint32 bh[4], bl[4];
                uint32 bb = (uint32)(((n0 + brow)*SKP + kk + b_koff) << 1);
                LDSM4(bh[0],bh[1],bh[2],bh[3], sBh + bb);
                LDSM4(bl[0],bl[1],bl[2],bl[3], sBl + bb);
                #pragma unroll
                for (int mt = 0; mt < 2; mt++)
                    MMA_TERMS(acc[mt*4+g*2], acc[mt*4+g*2+1], ah[mt], al[mt], bh, bl);
            }
        }
    }

    float* P = part + ((long)s*Bq + b)*Nq*Mq;
    const int erow = (lane >> 2), ecol = (lane & 3) << 1;
    #pragma unroll
    for (int mt = 0; mt < 2; mt++) {
        int r0 = m0 + mt*16 + erow;
        #pragma unroll
        for (int g = 0; g < 2; g++)
            #pragma unroll
            for (int hcol = 0; hcol < 2; hcol++) {
                int t = mt*4 + g*2 + hcol;
                int col = cg*32 + g*16 + hcol*8 + ecol;
                *(float2*)&P[r0*64 + col]     = make_float2(acc[t][0], acc[t][1]);
                *(float2*)&P[(r0+8)*64 + col] = make_float2(acc[t][2], acc[t][3]);
            }
    }
}

// ---- ONE merged prep kernel (transposes, packs, init_h) --------------------
#define W3P_N (KO*64)
#define GRU_N (64*192)
#define W1_N  (256*128)
#define W2_N  (128*256)
#define IH_N  (NNODE*64)
#define PREP_TOTAL (W3P_N + GRU_N + W1_N + W2_N + IH_N)

__global__ void prep_all(const float* __restrict__ We3,
                         const float* __restrict__ Wih, const float* __restrict__ Whh,
                         const float* __restrict__ We1, const float* __restrict__ We2,
                         const float* __restrict__ h_in,
                         uint32* __restrict__ w3p,
                         float* __restrict__ WihT, float* __restrict__ WhhT,
                         uint32* __restrict__ w1p, uint32* __restrict__ w2p,
                         float* __restrict__ h, uint32* __restrict__ hp)
{
    int idx = blockIdx.x*256 + threadIdx.x;
    if (idx < W3P_N) {
        int n = idx>>6, i = idx&63;
        w3p[idx] = packsplit(We3[(long)(n>>6)*4096 + (n&63)*64 + i]);
    } else if (idx < W3P_N + GRU_N) {
        int j2 = idx - W3P_N;
        int i = j2/192, j = j2%192;
        WihT[j2] = Wih[j*64+i];
        WhhT[j2] = Whh[j*64+i];
    } else if (idx < W3P_N + GRU_N + W1_N) {
        int i = idx - W3P_N - GRU_N;
        int n = i >> 7, k = i & 127;
        w1p[i] = packsplit(We1[k*256 + n]);
    } else if (idx < W3P_N + GRU_N + W1_N + W2_N) {
        int j = idx - W3P_N - GRU_N - W1_N;
        int n = j >> 8, k = j & 255;
        w2p[j] = packsplit(We2[k*128 + n]);
    } else if (idx < PREP_TOTAL) {
        int j = idx - W3P_N - GRU_N - W1_N - W2_N;
        int node = j>>6, i = j&63;
        float v = (i<INq) ? h_in[node*INq+i] : 0.f;
        h[j] = v;
        hp[j] = packsplit(v);
    }
}

// ============ fp32 FFMA2 SGEMM body (device inline) ========================
template<int ACT, int PACKOUT>
__device__ __forceinline__
void gemm128_body(const float* __restrict__ A, const float* __restrict__ Bm,
                  const float* __restrict__ bias, void* __restrict__ Cv,
                  int Nc, int K, float As[16][132], float Bs[16][128])
{
    const int bm = blockIdx.y*128, bn = blockIdx.x*128;
    const int tid = threadIdx.x;
    const int tr = tid>>4, tc = tid&15;

    ull acc[8][4];
    #pragma unroll
    for (int i=0;i<8;i++)
        #pragma unroll
        for (int j=0;j<4;j++) acc[i][j]=0ull;

    float4 pa[2], pb[2];
    const int ntiles = K>>4;

    #pragma unroll
    for (int i=0;i<2;i++){
        int l = tid + i*256; int q = l&3, r = l>>2;
        pa[i] = *(const float4*)&A[(long)(bm+r)*K + q*4];
    }
    #pragma unroll
    for (int i=0;i<2;i++){
        int l = tid + i*256; int r = l>>5, c = (l&31)*4;
        pb[i] = *(const float4*)&Bm[(long)r*Nc + bn + c];
    }
    #pragma unroll
    for (int i=0;i<2;i++){
        int l = tid + i*256; int q = l&3, r = l>>2;
        As[q*4+0][r]=pa[i].x; As[q*4+1][r]=pa[i].y;
        As[q*4+2][r]=pa[i].z; As[q*4+3][r]=pa[i].w;
    }
    #pragma unroll
    for (int i=0;i<2;i++){
        int l = tid + i*256; int r = l>>5, c = (l&31)*4;
        *(float4*)&Bs[r][c] = pb[i];
    }
    __syncthreads();

    for (int t=0; t<ntiles; t++){
        if (t+1 < ntiles){
            int kt = (t+1)<<4;
            #pragma unroll
            for (int i=0;i<2;i++){
                int l = tid + i*256; int q = l&3, r = l>>2;
                pa[i] = *(const float4*)&A[(long)(bm+r)*K + kt + q*4];
            }
            #pragma unroll
            for (int i=0;i<2;i++){
                int l = tid + i*256; int r = l>>5, c = (l&31)*4;
                pb[i] = *(const float4*)&Bm[(long)(kt+r)*Nc + bn + c];
            }
        }
        #pragma unroll
        for (int k=0;k<16;k++){
            float4 a0 = *(const float4*)&As[k][tr*8];
            float4 a1 = *(const float4*)&As[k][tr*8+4];
            ulonglong2 bb0 = *(const ulonglong2*)&Bs[k][tc*8];
            ulonglong2 bb1 = *(const ulonglong2*)&Bs[k][tc*8+4];
            ull bp0=bb0.x, bp1=bb0.y, bp2=bb1.x, bp3=bb1.y;
            ull a2[8];
            PACK_DUP(a2[0], a0.x); PACK_DUP(a2[1], a0.y);
            PACK_DUP(a2[2], a0.z); PACK_DUP(a2[3], a0.w);
            PACK_DUP(a2[4], a1.x); PACK_DUP(a2[5], a1.y);
            PACK_DUP(a2[6], a1.z); PACK_DUP(a2[7], a1.w);
            #pragma unroll
            for (int i=0;i<8;i++){
                FMA_X2(acc[i][0], a2[i], bp0);
                FMA_X2(acc[i][1], a2[i], bp1);
                FMA_X2(acc[i][2], a2[i], bp2);
                FMA_X2(acc[i][3], a2[i], bp3);
            }
        }
        __syncthreads();
        if (t+1 < ntiles){
            #pragma unroll
            for (int i=0;i<2;i++){
                int l = tid + i*256; int q = l&3, r = l>>2;
                As[q*4+0][r]=pa[i].x; As[q*4+1][r]=pa[i].y;
                As[q*4+2][r]=pa[i].z; As[q*4+3][r]=pa[i].w;
            }
            #pragma unroll
            for (int i=0;i<2;i++){
                int l = tid + i*256; int r = l>>5, c = (l&31)*4;
                *(float4*)&Bs[r][c] = pb[i];
            }
            __syncthreads();
        }
    }

    const int gc0 = bn + tc*8;
    float bv[8];
    #pragma unroll
    for (int j=0;j<8;j++) bv[j] = bias ? bias[gc0+j] : 0.f;
    #pragma unroll
    for (int i=0;i<8;i++){
        int gr = bm + tr*8 + i;
        float o[8];
        #pragma unroll
        for (int j=0;j<4;j++){
            unsigned lo, hi;
            UNPACK2(lo, hi, acc[i][j]);
            o[2*j]   = __uint_as_float(lo) + bv[2*j];
            o[2*j+1] = __uint_as_float(hi) + bv[2*j+1];
        }
        if (ACT==1){
            #pragma unroll
            for (int j=0;j<8;j++) o[j] = fmaxf(o[j], 0.f);
        }
        if (PACKOUT==0){
            float* C = (float*)Cv;
            *(float4*)&C[(long)gr*Nc + gc0]     = make_float4(o[0],o[1],o[2],o[3]);
            *(float4*)&C[(long)gr*Nc + gc0 + 4] = make_float4(o[4],o[5],o[6],o[7]);
        } else {
            uint32* C = (uint32*)Cv;
            uint4 s0 = make_uint4(packsplit(o[0]),packsplit(o[1]),packsplit(o[2]),packsplit(o[3]));
            uint4 s1 = make_uint4(packsplit(o[4]),packsplit(o[5]),packsplit(o[6]),packsplit(o[7]));
            *(uint4*)&C[(long)gr*Nc + gc0]     = s0;
            *(uint4*)&C[(long)gr*Nc + gc0 + 4] = s1;
        }
    }
}

// dual readout GEMM: z selects (gate chain, val chain) operands; relu epilogue
__global__ __launch_bounds__(256)
void gemm128_dualro(const float* __restrict__ A0, const float* __restrict__ B0,
                    const float* __restrict__ bias0, float* __restrict__ C0, int K0,
                    const float* __restrict__ A1, const float* __restrict__ B1,
                    const float* __restrict__ bias1, float* __restrict__ C1, int K1,
                    int Nc)
{
    __shared__ __align__(16) float As[16][132];
    __shared__ __align__(16) float Bs[16][128];
    if (blockIdx.z == 0)
        gemm128_body<1,0>(A0, B0, bias0, C0, Nc, K0, As, Bs);
    else
        gemm128_body<1,0>(A1, B1, bias1, C1, Nc, K1, As, Bs);
}

// ---------------- generic tiled SGEMM body (bounds-checked) ----------------
template<int ACT>
__device__ __forceinline__
void gemm64_body(const float* __restrict__ A, const float* __restrict__ Bm,
                 const float* __restrict__ bias, float* __restrict__ C,
                 int Mr, int Nc, int K,
                 float As[16][65], float Bs[16][64])
{
    const int BM=64, BN=64, BK=16;
    int bm = blockIdx.y*BM, bn = blockIdx.x*BN;
    int tid = threadIdx.x;
    int tr = tid>>4, tc = tid&15;
    float acc[4][4] = {};
    for (int kt=0; kt<K; kt+=BK) {
        #pragma unroll
        for (int i=0;i<4;i++){
            int l = tid + i*256; int r = l>>4, c = l&15;
            int gr = bm+r, gc = kt+c;
            As[c][r] = (gr<Mr && gc<K) ? A[(long)gr*K + gc] : 0.f;
        }
        #pragma unroll
        for (int i=0;i<4;i++){
            int l = tid + i*256; int r = l>>6, c = l&63;
            int gr = kt+r, gc = bn+c;
            Bs[r][c] = (gr<K && gc<Nc) ? Bm[(long)gr*Nc + gc] : 0.f;
        }
        __syncthreads();
        #pragma unroll
        for (int k=0;k<BK;k++){
            float a[4], b[4];
            #pragma unroll
            for (int i=0;i<4;i++) a[i]=As[k][tr*4+i];
            #pragma unroll
            for (int j=0;j<4;j++) b[j]=Bs[k][tc*4+j];
            #pragma unroll
            for (int i=0;i<4;i++)
                #pragma unroll
                for (int j=0;j<4;j++) acc[i][j] = fmaf(a[i],b[j],acc[i][j]);
        }
        __syncthreads();
    }
    #pragma unroll
    for (int i=0;i<4;i++){
        int gr = bm + tr*4 + i;
        if (gr>=Mr) continue;
        #pragma unroll
        for (int j=0;j<4;j++){
            int gc = bn + tc*4 + j;
            if (gc>=Nc) continue;
            float v = acc[i][j] + (bias?bias[gc]:0.f);
            if (ACT==1) v = fmaxf(v,0.f);
            C[(long)gr*Nc + gc] = v;
        }
    }
}

// dual final readout: z0: t1@Wi3->gatel ; z1: v1@Wj3->val  (N=32, K=128)
__global__ void gemm64_dualro(const float* __restrict__ t1, const float* __restrict__ Wi3,
                              const float* __restrict__ bi3, float* __restrict__ gatel,
                              const float* __restrict__ v1, const float* __restrict__ Wj3,
                              const float* __restrict__ bj3, float* __restrict__ val)
{
    __shared__ float As[16][65];
    __shared__ float Bs[16][64];
    if (blockIdx.z == 0)
        gemm64_body<0>(t1, Wi3, bi3, gatel, NNODE, 32, 128, As, Bs);
    else
        gemm64_body<0>(v1, Wj3, bj3, val, NNODE, 32, 128, As, Bs);
}

// single GRU-gate GEMM: C[2048,192] = A[2048,64] @ Bm[64,192] + bias
__global__ void gemm64_gate(const float* __restrict__ A, const float* __restrict__ Bm,
                            const float* __restrict__ bias, float* __restrict__ C)
{
    const int BM=64, BN=64, BK=16;
    const int Nc = 192, K = 64;

    __shared__ float As[BK][BM+1];
    __shared__ float Bs[BK][BN];
    int bm = blockIdx.y*BM, bn = blockIdx.x*BN;
    int tid = threadIdx.x;
    int tr = tid>>4, tc = tid&15;
    float acc[4][4] = {};
    for (int kt=0; kt<K; kt+=BK) {
        #pragma unroll
        for (int i=0;i<4;i++){
            int l = tid + i*256; int r = l>>4, c = l&15;
            As[c][r] = A[(long)(bm+r)*K + kt + c];
        }
        #pragma unroll
        for (int i=0;i<4;i++){
            int l = tid + i*256; int r = l>>6, c = l&63;
            int gc = bn+c;
            Bs[r][c] = (gc<Nc) ? Bm[(long)(kt+r)*Nc + gc] : 0.f;
        }
        __syncthreads();
        #pragma unroll
        for (int k=0;k<BK;k++){
            float a[4], b[4];
            #pragma unroll
            for (int i=0;i<4;i++) a[i]=As[k][tr*4+i];
            #pragma unroll
            for (int j=0;j<4;j++) b[j]=Bs[k][tc*4+j];
            #pragma unroll
            for (int i=0;i<4;i++)
                #pragma unroll
                for (int j=0;j<4;j++) acc[i][j] = fmaf(a[i],b[j],acc[i][j]);
        }
        __syncthreads();
    }
    #pragma unroll
    for (int i=0;i<4;i++){
        int gr = bm + tr*4 + i;
        #pragma unroll
        for (int j=0;j<4;j++){
            int gc = bn + tc*4 + j;
            if (gc>=Nc) continue;
            C[(long)gr*Nc + gc] = acc[i][j] + bias[gc];
        }
    }
}

__global__ void msg_reduce(const float* __restrict__ part, const float* __restrict__ bmsg,
                           float* __restrict__ msg)
{
    int idx = blockIdx.x*256 + threadIdx.x;
    if (idx >= NNODE*Mq) return;
    int node = idx>>6, o = idx&63;
    int b = node>>7, v = node&127;
    float s = bmsg[b*64+o];
    #pragma unroll 8
    for (int sp=0; sp<SPLITS; sp++)
        s += part[((long)sp*Bq + b)*Nq*Mq + v*64 + o];
    msg[idx]=s;
}

__global__ void bias_msg_kernel(const float* __restrict__ h, const float* __restrict__ be3,
                                float* __restrict__ bmsg)
{
    int b = blockIdx.x;
    __shared__ float hs[64];
    int t = threadIdx.x;
    float s = 0.f;
    for (int w=0; w<Nq; w++) s += h[((long)b*Nq+w)*64 + t];
    hs[t] = s;
    __syncthreads();
    float r = 0.f;
    for (int i=0;i<64;i++) r = fmaf(be3[t*64+i], hs[i], r);
    bmsg[b*64+t] = r;
}

__global__ void gru_update(const float* __restrict__ gi, const float* __restrict__ gh,
                           const int* __restrict__ g_size, float* __restrict__ h,
                           uint32* __restrict__ hp){
    int idx = blockIdx.x*256+threadIdx.x;
    if (idx>=NNODE*64) return;
    int node = idx>>6, i = idx&63;
    int b = node>>7, v = node&127;
    float r = 1.f/(1.f+expf(-(gi[node*192+i]     + gh[node*192+i])));
    float z = 1.f/(1.f+expf(-(gi[node*192+64+i]  + gh[node*192+64+i])));
    float n = tanhf(gi[node*192+128+i] + r*gh[node*192+128+i]);
    float hv = (1.f-z)*n + z*h[idx];
    hv = (v < g_size[b]) ? hv : 0.f;
    h[idx] = hv;
    hp[idx] = packsplit(hv);
}

__global__ void concat_kernel(const float* __restrict__ h, const float* __restrict__ h_in,
                              float* __restrict__ cat){
    int idx = blockIdx.x*256+threadIdx.x;
    if (idx>=NNODE*96) return;
    int node=idx/96, c=idx%96;
    cat[idx] = (c<64)? h[node*64+c] : h_in[node*INq + (c-64)];
}

__global__ void res_reduce(const float* __restrict__ gatel, const float* __restrict__ val,
                           const int* __restrict__ g_size, float* __restrict__ res){
    int t = blockIdx.x, b = blockIdx.y;
    int tid = threadIdx.x;
    int gs = g_size[b];
    float s = 0.f;
    if (tid < gs) {
        int node = b*Nq+tid;
        float gl = gatel[node*Tq+t];
        s = (1.f/(1.f+expf(-gl))) * val[node*Tq+t];
    }
    __shared__ float sm[128];
    sm[tid]=s; __syncthreads();
    for (int st=64; st>0; st>>=1){ if(tid<st) sm[tid]+=sm[tid+st]; __syncthreads(); }
    if (tid==0) res[b*Tq+t]=sm[0];
}

__global__ void logsoftmax_kernel(const float* __restrict__ res, float* __restrict__ out){
    int b = blockIdx.x; int t = threadIdx.x;
    float x = res[b*Tq+t];
    float m = x;
    for (int o=16;o>0;o>>=1) m = fmaxf(m, __shfl_xor_sync(0xffffffffu, m, o));
    float e = expf(x-m), s=e;
    for (int o=16;o>0;o>>=1) s += __shfl_xor_sync(0xffffffffu, s, o);
    out[b*Tq+t] = x - m - logf(s);
}

// ---------------------------------------------------------------------------
static inline void* symp(const void* symbol){
    void* p = nullptr;
    cudaGetSymbolAddress(&p, symbol);
    return p;
}

extern "C" void kernel_launch(void* const* d_in, const int* in_sizes, int n_in,
                              void* d_out, int out_size)
{
    const float* h_in = (const float*)d_in[0];
    const float* am   = (const float*)d_in[1];
    const int*   gsz  = (const int*)d_in[2];
    const float* We0=(const float*)d_in[3];  const float* be0=(const float*)d_in[4];
    const float* We1=(const float*)d_in[5];  const float* be1=(const float*)d_in[6];
    const float* We2=(const float*)d_in[7];  const float* be2=(const float*)d_in[8];
    const float* We3=(const float*)d_in[9];  const float* be3=(const float*)d_in[10];
    const float* Wih=(const float*)d_in[11]; const float* Whh=(const float*)d_in[12];
    const float* bih=(const float*)d_in[13]; const float* bhh=(const float*)d_in[14];
    const float* Wi0=(const float*)d_in[15]; const float* bi0=(const float*)d_in[16];
    const float* Wj0=(const float*)d_in[17]; const float* bj0=(const float*)d_in[18];
    const float* Wi1=(const float*)d_in[19]; const float* bi1=(const float*)d_in[20];
    const float* Wj1=(const float*)d_in[21]; const float* bj1=(const float*)d_in[22];
    const float* Wi2=(const float*)d_in[23]; const float* bi2=(const float*)d_in[24];
    const float* Wj2=(const float*)d_in[25]; const float* bj2=(const float*)d_in[26];
    const float* Wi3=(const float*)d_in[27]; const float* bi3=(const float*)d_in[28];
    const float* Wj3=(const float*)d_in[29]; const float* bj3=(const float*)d_in[30];
    (void)in_sizes; (void)n_in; (void)out_size;

    uint32* e256p= (uint32*)symp(d_e256p);
    uint32* fp   = (uint32*)symp(d_fp);
    uint32* w1p  = (uint32*)symp(d_w1p);
    uint32* w2p  = (uint32*)symp(d_w2p);
    uint32* w3p  = (uint32*)symp(d_w3p);
    uint32* g    = (uint32*)symp(d_g);
    float* h    = (float*)symp(d_h);
    uint32* hp   = (uint32*)symp(d_hp);
    float* part = (float*)symp(d_part);  float* msg  = (float*)symp(d_msg);
    float* gi   = (float*)symp(d_gi);    float* gh   = (float*)symp(d_gh);
    float* WihT = (float*)symp(d_WihT);
    float* WhhT = (float*)symp(d_WhhT);  float* bmsg = (float*)symp(d_bmsg);
    float* cat  = (float*)symp(d_cat);   float* t1   = (float*)symp(d_t1);
    float* t2   = (float*)symp(d_t2);    float* v1   = (float*)symp(d_v1);
    float* v2   = (float*)symp(d_v2);    float* gatel= (float*)symp(d_gatel);
    float* val  = (float*)symp(d_val);   float* res  = (float*)symp(d_res);
    float* out  = (float*)d_out;

    // one-time host-side resources (created on first, uncaptured, call)
    static cudaStream_t s2 = nullptr;
    static cudaEvent_t evFork[4] = {nullptr,nullptr,nullptr,nullptr};
    static cudaEvent_t evJoin[4] = {nullptr,nullptr,nullptr,nullptr};
    if (!s2) {
        cudaStreamCreateWithFlags(&s2, cudaStreamNonBlocking);
        for (int i = 0; i < 4; i++) {
            cudaEventCreateWithFlags(&evFork[i], cudaEventDisableTiming);
            cudaEventCreateWithFlags(&evJoin[i], cudaEventDisableTiming);
        }
        cudaFuncSetAttribute(mlp1_mma64,
                             cudaFuncAttributeMaxDynamicSharedMemorySize, M64_SMEM);
        cudaFuncSetAttribute(mlp2_mma64,
                             cudaFuncAttributeMaxDynamicSharedMemorySize, M64_SMEM);
        cudaFuncSetAttribute(splitk_mma,
                             cudaFuncAttributeMaxDynamicSharedMemorySize, SPLITK_SMEM);
        cudaFuncSetAttribute(gmma,
                             cudaFuncAttributeMaxDynamicSharedMemorySize, GMMA_SMEM);
    }

    // merged prep (weight packs/transposes + init_h/hp, 1 launch)
    prep_all<<<(PREP_TOTAL+255)/256,256>>>(We3, Wih, Whh, We1, We2, h_in,
                                           w3p, WihT, WhhT, w1p, w2p, h, hp);

    // fork 0: layer-0 message prep + gh-gemm (need only prep_all) overlap MLP
    cudaEventRecord(evFork[0], 0);
    cudaStreamWaitEvent(s2, evFork[0], 0);
    gmma<<<dim3(64,32),256,GMMA_SMEM,s2>>>(hp, w3p, g);
    bias_msg_kernel<<<Bq,64,0,s2>>>(h, be3, bmsg);
    gemm64_gate<<<dim3(3,32),256,0,s2>>>(h, WhhT, bhh, gh);
    cudaEventRecord(evJoin[0], s2);

    // edge MLP: 4 -> 128 -> 256 -> 128 (relu each), on main stream
    mlp1_mma64<<<NE/64,256,M64_SMEM>>>(am, We0, be0, w1p, be1, e256p);
    mlp2_mma64<<<NE/64,256,M64_SMEM>>>(e256p, w2p, be2, fp);

    cudaStreamWaitEvent(0, evJoin[0], 0);

    for (int layer=0; layer<3; layer++) {
        if (layer > 0) {
            // fork: bias_msg + gh-gemm (depend only on h) overlap gmma+splitk
            cudaEventRecord(evFork[layer], 0);
            cudaStreamWaitEvent(s2, evFork[layer], 0);
            bias_msg_kernel<<<Bq,64,0,s2>>>(h, be3, bmsg);
            gemm64_gate<<<dim3(3,32),256,0,s2>>>(h, WhhT, bhh, gh);
            cudaEventRecord(evJoin[layer], s2);
            gmma<<<dim3(64,32),256,GMMA_SMEM>>>(hp, w3p, g);
        }
        splitk_mma<<<dim3(SPLITS,Bq), 256, SPLITK_SMEM>>>(fp, g, part);
        if (layer > 0) cudaStreamWaitEvent(0, evJoin[layer], 0);
        msg_reduce<<<512,256>>>(part, bmsg, msg);
        gemm64_gate<<<dim3(3,32),256>>>(msg, WihT, bih, gi);
        gru_update<<<512,256>>>(gi, gh, gsz, h, hp);
    }

    // readout: gate & val chains fused per layer via blockIdx.z
    concat_kernel<<<768,256>>>(h, h_in, cat);
    gemm128_dualro<<<dim3(1,16,2), 256>>>(cat, Wi0, bi0, t1, 96,
                                          h,   Wj0, bj0, v1, 64, 128);
    gemm128_dualro<<<dim3(2,16,2), 256>>>(t1, Wi1, bi1, t2, 128,
                                          v1, Wj1, bj1, v2, 128, 256);
    gemm128_dualro<<<dim3(1,16,2), 256>>>(t2, Wi2, bi2, t1, 256,
                                          v2, Wj2, bj2, v1, 256, 128);
    gemm64_dualro<<<dim3(1,32,2), 256>>>(t1, Wi3, bi3, gatel,
                                         v1, Wj3, bj3, val);

    res_reduce<<<dim3(Tq,Bq),128>>>(gatel, val, gsz, res);
    logsoftmax_kernel<<<Bq,Tq>>>(res, out);
}